// round 10
// baseline (speedup 1.0000x reference)
#include <cuda_runtime.h>
#include <cstdint>

#define Nn   2048
#define IND  128
#define HIDD 64
#define Ee   32768
#define EPSf 1e-5f
#define NOUT 4096   /* HIDD*HIDD */

// -------- scratch (device globals; no allocation allowed) --------
__device__ __align__(256) float g_p1[Nn * NOUT];     // relu(h@W1+b1)
__device__ __align__(256) float g_p2[Nn * HIDD];     // relu(h@Wp2+bp2)
__device__ __align__(256) float g_u[Nn * IND];       // src-half conv of LN(local)
__device__ __align__(256) float g_v[Nn * IND];       // dst-half conv of LN(local)
__device__ __align__(256) uint32_t g_wghi[HIDD * HIDD];  // tf32 split of Wg
__device__ __align__(256) uint32_t g_wglo[HIDD * HIDD];
__device__ __align__(256) uint4 g_w2pk[HIDD * 64];   // packed tf32 split of W2 [n][kb*4+t]
__device__ __align__(256) float g_C[HIDD];
__device__ int g_off[Nn + 1];
__device__ int g_eidx[Ee];

// ================= tf32 helpers =================
__device__ __forceinline__ uint32_t f2tf(float x) {
    uint32_t r;
    asm("cvt.rna.tf32.f32 %0, %1;" : "=r"(r) : "f"(x));
    return r;
}
__device__ __forceinline__ void mma_tf32(float* d, const uint32_t* a, const uint32_t* b) {
    asm volatile(
        "mma.sync.aligned.m16n8k8.row.col.f32.tf32.tf32.f32 "
        "{%0,%1,%2,%3}, {%4,%5,%6,%7}, {%8,%9}, {%0,%1,%2,%3};"
        : "+f"(d[0]), "+f"(d[1]), "+f"(d[2]), "+f"(d[3])
        : "r"(a[0]), "r"(a[1]), "r"(a[2]), "r"(a[3]), "r"(b[0]), "r"(b[1]));
}

// ================= fused bucketing =================
__global__ __launch_bounds__(1024) void k_bucket(const int* __restrict__ src) {
    __shared__ int cnt[Nn];
    __shared__ int warpsum[32];
    int t = threadIdx.x;
    cnt[t] = 0;
    cnt[t + 1024] = 0;
    __syncthreads();
    for (int e = t; e < Ee; e += 1024) atomicAdd(&cnt[src[e]], 1);
    __syncthreads();

    int c0 = cnt[2 * t], c1 = cnt[2 * t + 1];
    int s = c0 + c1;
    int lane = t & 31, warp = t >> 5;
    int v = s;
#pragma unroll
    for (int o = 1; o < 32; o <<= 1) {
        int u = __shfl_up_sync(0xffffffffu, v, o);
        if (lane >= o) v += u;
    }
    if (lane == 31) warpsum[warp] = v;
    __syncthreads();
    if (warp == 0) {
        int w = warpsum[lane];
#pragma unroll
        for (int o = 1; o < 32; o <<= 1) {
            int u = __shfl_up_sync(0xffffffffu, w, o);
            if (lane >= o) w += u;
        }
        warpsum[lane] = w;
    }
    __syncthreads();
    int excl = v - s + (warp ? warpsum[warp - 1] : 0);
    g_off[2 * t] = excl;
    g_off[2 * t + 1] = excl + c0;
    if (t == 1023) g_off[Nn] = excl + s;
    __syncthreads();
    cnt[2 * t] = excl;
    cnt[2 * t + 1] = excl + c0;
    __syncthreads();
    for (int e = t; e < Ee; e += 1024) {
        int p = atomicAdd(&cnt[src[e]], 1);
        g_eidx[p] = e;
    }
}

// ================= prep: Wg split + C + packed W2 =================
__global__ void k_prep(const float* __restrict__ W3,
                       const float* __restrict__ b3,
                       const float* __restrict__ bng_g,
                       const float* __restrict__ bng_b,
                       const float* __restrict__ bnG_g,
                       const float* __restrict__ bnG_b,
                       const float* __restrict__ W2) {
    int idx = blockIdx.x * blockDim.x + threadIdx.x;
    float rs = rsqrtf(1.f + EPSf);
    if (idx < 4096) {
        int d = idx >> 6, dp = idx & 63;
        float wg = (bng_g[d] * rs) * W3[idx] * (bnG_g[dp] * rs);
        uint32_t hi = f2tf(wg);
        g_wghi[idx] = hi;
        g_wglo[idx] = f2tf(wg - __uint_as_float(hi));
    } else if (idx < 4096 + 1024) {
        int j = idx - 4096;
        int n = j & 63, kb = j >> 6;            // coalesced over n
        uint32_t hi[8], lo[8];
#pragma unroll
        for (int jj = 0; jj < 8; jj++) {
            float x = W2[(kb * 8 + jj) * HIDD + n];
            hi[jj] = f2tf(x);
            lo[jj] = f2tf(x - __uint_as_float(hi[jj]));
        }
#pragma unroll
        for (int tq = 0; tq < 4; tq++)
            g_w2pk[n * 64 + kb * 4 + tq] = make_uint4(hi[tq], hi[tq + 4], lo[tq], lo[tq + 4]);
    } else if (idx < 4096 + 1024 + 64) {
        int dp = idx - 5120;
        float s = 0.f;
        for (int d = 0; d < 64; d++) s += bng_b[d] * W3[d * 64 + dp];
        g_C[dp] = (s + b3[dp]) * (bnG_g[dp] * rs) + bnG_b[dp];
    }
}

// ================= node prep: LN(local[i]) -> u[i], v[i] =================
__global__ __launch_bounds__(256) void k_nodeprep(const float* __restrict__ local,
                                                  const float* __restrict__ ln_w,
                                                  const float* __restrict__ ln_b,
                                                  const float* __restrict__ conv_w) {
    __shared__ float lns[2][IND + 2];
    __shared__ float2 red[2][4];
    int tid = threadIdx.x;
    int grp = tid >> 7, t = tid & 127;
    int node = blockIdx.x * 2 + grp;
    int lane = t & 31, warp = t >> 5;

    float x = local[node * IND + t];
    float2 v = make_float2(x, x * x);
#pragma unroll
    for (int o = 16; o; o >>= 1) {
        v.x += __shfl_down_sync(0xffffffffu, v.x, o);
        v.y += __shfl_down_sync(0xffffffffu, v.y, o);
    }
    if (lane == 0) red[grp][warp] = v;
    if (t == 0) { lns[grp][0] = 0.f; lns[grp][IND + 1] = 0.f; }
    __syncthreads();
    float2 tot = red[grp][0];
    tot.x += red[grp][1].x + red[grp][2].x + red[grp][3].x;
    tot.y += red[grp][1].y + red[grp][2].y + red[grp][3].y;
    float mu = tot.x * (1.f / IND);
    float var = tot.y * (1.f / IND) - mu * mu;
    float ln = (x - mu) * rsqrtf(var + EPSf) * ln_w[t] + ln_b[t];
    lns[grp][t + 1] = ln;
    __syncthreads();
    float l0 = lns[grp][t], l1 = lns[grp][t + 1], l2 = lns[grp][t + 2];
    g_u[node * IND + t] = conv_w[0] * l0 + conv_w[1] * l1 + conv_w[2] * l2;
    g_v[node * IND + t] = conv_w[3] * l0 + conv_w[4] * l1 + conv_w[5] * l2;
}

// ================= p1 GEMM: packed-tf32 mma, no cvt in mainloop =================
#define OFF_APK 0
#define OFF_BPK 73728
#define OFF_AST 147456
#define OFF_BST 182272
#define P1_SMEM 217088

__global__ __launch_bounds__(256) void k_p1pk(const float* __restrict__ h,
                                              const float* __restrict__ W1,
                                              const float* __restrict__ b1,
                                              const float* __restrict__ Wp2,
                                              const float* __restrict__ bp2) {
    extern __shared__ char smraw[];
    uint4* Apk = (uint4*)(smraw + OFF_APK);
    uint4* Bpk = (uint4*)(smraw + OFF_BPK);
    float* Ast = (float*)(smraw + OFF_AST);
    float* Bst = (float*)(smraw + OFF_BST);

    int tid = threadIdx.x;
    int wid = tid >> 5, lane = tid & 31;
    int g = lane >> 2, t = lane & 3;
    int warp_m = (wid >> 2) * 64;
    int warp_n = (wid & 3) * 32;
    int bx = blockIdx.x;
    int row0 = blockIdx.y * 128;
    int col0 = bx * 128;
    bool p2tile = (bx == 32);

    float acc[4][4][4];
#pragma unroll
    for (int mi = 0; mi < 4; mi++)
#pragma unroll
        for (int ni = 0; ni < 4; ni++)
#pragma unroll
            for (int r = 0; r < 4; r++) acc[mi][ni][r] = 0.f;

    for (int kc = 0; kc < IND; kc += 64) {
#pragma unroll
        for (int it = 0; it < 8; it++) {
            int chunk = tid + it * 256;
            int m = chunk >> 4;
            int k4 = (chunk & 15) * 4;
            float4 v = *(const float4*)&h[(row0 + m) * IND + kc + k4];
            *(float4*)&Ast[m * 68 + k4] = v;
        }
#pragma unroll
        for (int it = 0; it < 8; it++) {
            int chunk = tid + it * 256;
            int k = chunk >> 5;
            int n4 = (chunk & 31) * 4;
            float4 v;
            if (!p2tile) {
                v = *(const float4*)&W1[(kc + k) * NOUT + col0 + n4];
            } else if (n4 < 64) {
                v = *(const float4*)&Wp2[(kc + k) * HIDD + n4];
            } else {
                v = make_float4(0.f, 0.f, 0.f, 0.f);
            }
            *(float4*)&Bst[k * 136 + n4] = v;
        }
        __syncthreads();

        {
            int kb = tid >> 5;
            int rb = tid & 31;
#pragma unroll
            for (int jr = 0; jr < 4; jr++) {
                int row = rb + jr * 32;
                uint32_t hi[8], lo[8];
#pragma unroll
                for (int j = 0; j < 8; j++) {
                    float x = Ast[row * 68 + kb * 8 + j];
                    hi[j] = f2tf(x);
                    lo[j] = f2tf(x - __uint_as_float(hi[j]));
                }
#pragma unroll
                for (int tq = 0; tq < 4; tq++)
                    Apk[row * 36 + kb * 4 + tq] = make_uint4(hi[tq], hi[tq + 4], lo[tq], lo[tq + 4]);
            }
#pragma unroll
            for (int jn = 0; jn < 4; jn++) {
                int n = rb + jn * 32;
                uint32_t hi[8], lo[8];
#pragma unroll
                for (int j = 0; j < 8; j++) {
                    float x = Bst[(kb * 8 + j) * 136 + n];
                    hi[j] = f2tf(x);
                    lo[j] = f2tf(x - __uint_as_float(hi[j]));
                }
#pragma unroll
                for (int tq = 0; tq < 4; tq++)
                    Bpk[n * 36 + kb * 4 + tq] = make_uint4(hi[tq], hi[tq + 4], lo[tq], lo[tq + 4]);
            }
        }
        __syncthreads();

#pragma unroll 2
        for (int kb = 0; kb < 8; kb++) {
            uint4 afr[4][2];
            uint4 bfr[4];
#pragma unroll
            for (int mi = 0; mi < 4; mi++) {
                int r = warp_m + mi * 16 + g;
                afr[mi][0] = Apk[r * 36 + kb * 4 + t];
                afr[mi][1] = Apk[(r + 8) * 36 + kb * 4 + t];
            }
#pragma unroll
            for (int ni = 0; ni < 4; ni++) {
                int n = warp_n + ni * 8 + g;
                bfr[ni] = Bpk[n * 36 + kb * 4 + t];
            }
#pragma unroll
            for (int mi = 0; mi < 4; mi++) {
                uint32_t ah[4] = {afr[mi][0].x, afr[mi][1].x, afr[mi][0].y, afr[mi][1].y};
                uint32_t al[4] = {afr[mi][0].z, afr[mi][1].z, afr[mi][0].w, afr[mi][1].w};
#pragma unroll
                for (int ni = 0; ni < 4; ni++) {
                    uint32_t bh2[2] = {bfr[ni].x, bfr[ni].y};
                    uint32_t bl2[2] = {bfr[ni].z, bfr[ni].w};
                    mma_tf32(acc[mi][ni], ah, bh2);
                    mma_tf32(acc[mi][ni], ah, bl2);
                    mma_tf32(acc[mi][ni], al, bh2);
                }
            }
        }
        __syncthreads();
    }

    if (!p2tile) {
#pragma unroll
        for (int mi = 0; mi < 4; mi++) {
            int r = row0 + warp_m + mi * 16 + g;
#pragma unroll
            for (int ni = 0; ni < 4; ni++) {
                int c = col0 + warp_n + ni * 8 + t * 2;
                float2 bb = *(const float2*)&b1[c];
                float2 o0, o1;
                o0.x = fmaxf(acc[mi][ni][0] + bb.x, 0.f);
                o0.y = fmaxf(acc[mi][ni][1] + bb.y, 0.f);
                o1.x = fmaxf(acc[mi][ni][2] + bb.x, 0.f);
                o1.y = fmaxf(acc[mi][ni][3] + bb.y, 0.f);
                *(float2*)&g_p1[(size_t)r * NOUT + c] = o0;
                *(float2*)&g_p1[(size_t)(r + 8) * NOUT + c] = o1;
            }
        }
    } else {
#pragma unroll
        for (int mi = 0; mi < 4; mi++) {
            int r = row0 + warp_m + mi * 16 + g;
#pragma unroll
            for (int ni = 0; ni < 4; ni++) {
                int c = warp_n + ni * 8 + t * 2;
                if (c < HIDD) {
                    float2 bb = *(const float2*)&bp2[c];
                    float2 o0, o1;
                    o0.x = fmaxf(acc[mi][ni][0] + bb.x, 0.f);
                    o0.y = fmaxf(acc[mi][ni][1] + bb.y, 0.f);
                    o1.x = fmaxf(acc[mi][ni][2] + bb.x, 0.f);
                    o1.y = fmaxf(acc[mi][ni][3] + bb.y, 0.f);
                    *(float2*)&g_p2[r * HIDD + c] = o0;
                    *(float2*)&g_p2[(r + 8) * HIDD + c] = o1;
                }
            }
        }
    }
}

// ================= local branch v3: fully packed, zero cvt in mainloop =================
#define TPK_STR 68   /* uint4 stride, = 4 mod 8 -> same conflict pattern as p1pk */
#define L3_SMEM ((32 * TPK_STR + 64 * TPK_STR) * 16)   /* 34816 + 69632 = 104448 */

__global__ __launch_bounds__(256) void k_local3(const int* __restrict__ src,
                                                const int* __restrict__ dst,
                                                const float* __restrict__ conv_b,
                                                const float* __restrict__ b2,
                                                const float* __restrict__ bnL_g,
                                                const float* __restrict__ bnL_b,
                                                const float* __restrict__ ein,
                                                float* __restrict__ out) {
    extern __shared__ char smraw[];
    uint4* Tpk = (uint4*)smraw;                          // [32][TPK_STR]
    uint4* W2p = (uint4*)(smraw + 32 * TPK_STR * 16);    // [64][TPK_STR]

    int tid = threadIdx.x;
    int e0 = blockIdx.x * 32;
    float cb = conv_b[0];

    // build T packed: each thread does 8 consecutive k of one edge row
#pragma unroll
    for (int it = 0; it < 2; it++) {
        int idx = tid + it * 256;                        // e*16 + kb
        int e = idx >> 4, kb = idx & 15;
        int se = src[e0 + e], de = dst[e0 + e];
        const float4* pu = (const float4*)&g_u[se * IND + kb * 8];
        const float4* pv = (const float4*)&g_v[de * IND + kb * 8];
        float4 u0 = pu[0], u1 = pu[1], v0 = pv[0], v1 = pv[1];
        float xv[8] = {u0.x + v0.x + cb, u0.y + v0.y + cb, u0.z + v0.z + cb, u0.w + v0.w + cb,
                       u1.x + v1.x + cb, u1.y + v1.y + cb, u1.z + v1.z + cb, u1.w + v1.w + cb};
        uint32_t hi[8], lo[8];
#pragma unroll
        for (int j = 0; j < 8; j++) {
            float x = fmaxf(xv[j], 0.f);
            hi[j] = f2tf(x);
            lo[j] = f2tf(x - __uint_as_float(hi[j]));
        }
#pragma unroll
        for (int tq = 0; tq < 4; tq++)
            Tpk[e * TPK_STR + kb * 4 + tq] = make_uint4(hi[tq], hi[tq + 4], lo[tq], lo[tq + 4]);
    }
    // load packed W2 (4096 uint4)
#pragma unroll
    for (int it = 0; it < 16; it++) {
        int idx = tid + it * 256;
        int n = idx >> 6, c = idx & 63;
        W2p[n * TPK_STR + c] = g_w2pk[n * 64 + c];
    }
    __syncthreads();

    // mma: T[32x128] @ W2[128x64]; 8 warps, warp tile 16x16, zero cvt
    int wid = tid >> 5, lane = tid & 31;
    int g = lane >> 2, t = lane & 3;
    int m0 = (wid & 1) * 16;
    int n0 = (wid >> 1) * 16;
    int r = m0 + g;

    float acc[2][4];
#pragma unroll
    for (int ni = 0; ni < 2; ni++)
#pragma unroll
        for (int q = 0; q < 4; q++) acc[ni][q] = 0.f;

#pragma unroll 4
    for (int kb = 0; kb < 16; kb++) {
        uint4 a0 = Tpk[r * TPK_STR + kb * 4 + t];
        uint4 a1 = Tpk[(r + 8) * TPK_STR + kb * 4 + t];
        uint32_t ah[4] = {a0.x, a1.x, a0.y, a1.y};
        uint32_t al[4] = {a0.z, a1.z, a0.w, a1.w};
#pragma unroll
        for (int ni = 0; ni < 2; ni++) {
            uint4 bfr = W2p[(n0 + ni * 8 + g) * TPK_STR + kb * 4 + t];
            uint32_t bh2[2] = {bfr.x, bfr.y};
            uint32_t bl2[2] = {bfr.z, bfr.w};
            mma_tf32(acc[ni], ah, bh2);
            mma_tf32(acc[ni], ah, bl2);
            mma_tf32(acc[ni], al, bh2);
        }
    }

    float rs = rsqrtf(1.f + EPSf);
    int ea = e0 + m0 + g, eb = ea + 8;
#pragma unroll
    for (int ni = 0; ni < 2; ni++) {
        int c = n0 + ni * 8 + t * 2;
        float2 bb = *(const float2*)&b2[c];
        float2 gg = *(const float2*)&bnL_g[c];
        float2 bL = *(const float2*)&bnL_b[c];
        float2 ia = *(const float2*)&ein[ea * HIDD + c];
        float2 ib = *(const float2*)&ein[eb * HIDD + c];
        float2 oa, ob;
        oa.x = fmaxf((acc[ni][0] + bb.x) * (gg.x * rs) + bL.x, 0.f) + ia.x;
        oa.y = fmaxf((acc[ni][1] + bb.y) * (gg.y * rs) + bL.y, 0.f) + ia.y;
        ob.x = fmaxf((acc[ni][2] + bb.x) * (gg.x * rs) + bL.x, 0.f) + ib.x;
        ob.y = fmaxf((acc[ni][3] + bb.y) * (gg.y * rs) + bL.y, 0.f) + ib.y;
        *(float2*)&out[ea * HIDD + c] = oa;
        *(float2*)&out[eb * HIDD + c] = ob;
    }
}

// ================= global branch fused =================
#define GA_STR 68
#define ECAP 64
#define GO_AS  0
#define GO_BHI (64 * GA_STR * 4)
#define GO_BLO (GO_BHI + 64 * 72 * 4)
#define GO_P2  (GO_BLO + 64 * 72 * 4)
#define GO_EIX (GO_P2 + ECAP * 64 * 4)
#define G2_SMEM (GO_EIX + ECAP * 4)

__global__ __launch_bounds__(256) void k_global2(const int* __restrict__ dst,
                                                 float* __restrict__ out) {
    extern __shared__ char smraw[];
    float* As = (float*)(smraw + GO_AS);
    float* Gs = As;
    uint32_t* Bhi = (uint32_t*)(smraw + GO_BHI);
    uint32_t* Blo = (uint32_t*)(smraw + GO_BLO);
    float* p2buf = (float*)(smraw + GO_P2);
    int* eixs = (int*)(smraw + GO_EIX);

    int node = blockIdx.x;
    int tid = threadIdx.x;
    int beg = g_off[node], end = g_off[node + 1];
    if (beg == end) return;

    int ec = min(end - beg, ECAP);
    for (int idx = tid; idx < ec * 64; idx += 256) {
        int ei = idx >> 6, d2 = idx & 63;
        int e = g_eidx[beg + ei];
        if (d2 == 0) eixs[ei] = e;
        p2buf[idx] = g_p2[dst[e] * HIDD + d2];
    }

    const float* p1row = &g_p1[(size_t)node * NOUT];
#pragma unroll
    for (int it = 0; it < 16; it++) {
        int idx = tid + it * 256;
        int d = idx >> 6, k = idx & 63;
        As[k * GA_STR + d] = p1row[idx];
    }
#pragma unroll
    for (int it = 0; it < 16; it++) {
        int idx = tid + it * 256;
        int d = idx >> 6, dp = idx & 63;
        Bhi[d * 72 + dp] = g_wghi[idx];
        Blo[d * 72 + dp] = g_wglo[idx];
    }
    __syncthreads();

    int wid = tid >> 5, lane = tid & 31;
    int g = lane >> 2, t = lane & 3;
    int m0 = (wid & 3) * 16;
    int n0 = (wid >> 2) * 32;

    float acc[4][4];
#pragma unroll
    for (int ni = 0; ni < 4; ni++)
#pragma unroll
        for (int r = 0; r < 4; r++) acc[ni][r] = 0.f;

#pragma unroll
    for (int ks = 0; ks < 64; ks += 8) {
        uint32_t ahi[4], alo[4], bh[4][2], bl[4][2];
        int r = m0 + g;
        float a0 = As[r * GA_STR + ks + t];
        float a1 = As[(r + 8) * GA_STR + ks + t];
        float a2 = As[r * GA_STR + ks + t + 4];
        float a3 = As[(r + 8) * GA_STR + ks + t + 4];
        ahi[0] = f2tf(a0); alo[0] = f2tf(a0 - __uint_as_float(ahi[0]));
        ahi[1] = f2tf(a1); alo[1] = f2tf(a1 - __uint_as_float(ahi[1]));
        ahi[2] = f2tf(a2); alo[2] = f2tf(a2 - __uint_as_float(ahi[2]));
        ahi[3] = f2tf(a3); alo[3] = f2tf(a3 - __uint_as_float(ahi[3]));
#pragma unroll
        for (int ni = 0; ni < 4; ni++) {
            int n = n0 + ni * 8 + g;
            bh[ni][0] = Bhi[(ks + t) * 72 + n];
            bh[ni][1] = Bhi[(ks + t + 4) * 72 + n];
            bl[ni][0] = Blo[(ks + t) * 72 + n];
            bl[ni][1] = Blo[(ks + t + 4) * 72 + n];
        }
#pragma unroll
        for (int ni = 0; ni < 4; ni++) {
            mma_tf32(acc[ni], ahi, bh[ni]);
            mma_tf32(acc[ni], ahi, bl[ni]);
            mma_tf32(acc[ni], alo, bh[ni]);
        }
    }
    __syncthreads();

    int m = m0 + g;
#pragma unroll
    for (int ni = 0; ni < 4; ni++) {
        int n = n0 + ni * 8 + t * 2;
        Gs[m * 65 + n] = acc[ni][0];
        Gs[m * 65 + n + 1] = acc[ni][1];
        Gs[(m + 8) * 65 + n] = acc[ni][2];
        Gs[(m + 8) * 65 + n + 1] = acc[ni][3];
    }
    __syncthreads();

    int d = tid & 63, grp = tid >> 6;
    float Gr[64];
#pragma unroll
    for (int k = 0; k < 64; k++) Gr[k] = Gs[k * 65 + d];
    float Cd = g_C[d];

    int base = beg;
    while (true) {
        for (int e = grp; e < ec; e += 4) {
            const float4* p = (const float4*)&p2buf[e * 64];
            float a2 = 0.f;
#pragma unroll
            for (int k4 = 0; k4 < 16; k4++) {
                float4 v = p[k4];
                a2 += Gr[k4 * 4 + 0] * v.x + Gr[k4 * 4 + 1] * v.y
                    + Gr[k4 * 4 + 2] * v.z + Gr[k4 * 4 + 3] * v.w;
            }
            int eg = eixs[e];
            out[eg * HIDD + d] += fmaxf(a2 + Cd, 0.f);
        }
        base += ec;
        if (base >= end) break;
        __syncthreads();
        ec = min(end - base, ECAP);
        for (int idx = tid; idx < ec * 64; idx += 256) {
            int ei = idx >> 6, d2 = idx & 63;
            int e = g_eidx[base + ei];
            if (d2 == 0) eixs[ei] = e;
            p2buf[idx] = g_p2[dst[e] * HIDD + d2];
        }
        __syncthreads();
    }
}

// ================= launch =================
extern "C" void kernel_launch(void* const* d_in, const int* in_sizes, int n_in,
                              void* d_out, int out_size) {
    const float* h      = (const float*)d_in[0];
    const float* local_ = (const float*)d_in[1];
    const float* ein    = (const float*)d_in[2];
    const int*   src    = (const int*)d_in[3];
    const int*   dst    = (const int*)d_in[4];
    const float* ln_w   = (const float*)d_in[5];
    const float* ln_b   = (const float*)d_in[6];
    const float* conv_w = (const float*)d_in[7];
    const float* conv_b = (const float*)d_in[8];
    const float* W1     = (const float*)d_in[9];
    const float* b1     = (const float*)d_in[10];
    const float* Wp2    = (const float*)d_in[11];
    const float* bp2    = (const float*)d_in[12];
    const float* W2     = (const float*)d_in[13];
    const float* b2     = (const float*)d_in[14];
    const float* W3     = (const float*)d_in[15];
    const float* b3     = (const float*)d_in[16];
    const float* bng_g  = (const float*)d_in[17];
    const float* bng_b  = (const float*)d_in[18];
    const float* bnG_g  = (const float*)d_in[19];
    const float* bnG_b  = (const float*)d_in[20];
    const float* bnL_g  = (const float*)d_in[21];
    const float* bnL_b  = (const float*)d_in[22];
    float* out = (float*)d_out;

    static int smem_set = 0;
    if (!smem_set) {
        cudaFuncSetAttribute(k_p1pk, cudaFuncAttributeMaxDynamicSharedMemorySize, P1_SMEM);
        cudaFuncSetAttribute(k_local3, cudaFuncAttributeMaxDynamicSharedMemorySize, L3_SMEM);
        cudaFuncSetAttribute(k_global2, cudaFuncAttributeMaxDynamicSharedMemorySize, G2_SMEM);
        smem_set = 1;
    }

    k_bucket<<<1, 1024>>>(src);
    k_prep<<<21, 256>>>(W3, b3, bng_g, bng_b, bnG_g, bnG_b, W2);
    k_nodeprep<<<Nn / 2, 256>>>(local_, ln_w, ln_b, conv_w);
    k_p1pk<<<dim3(33, Nn / 128), 256, P1_SMEM>>>(h, W1, b1, Wp2, bp2);  // 4th -> profiled
    k_local3<<<Ee / 32, 256, L3_SMEM>>>(src, dst, conv_b, b2, bnL_g, bnL_b, ein, out);
    k_global2<<<Nn, 256, G2_SMEM>>>(dst, out);
}

// round 11
// speedup vs baseline: 1.0520x; 1.0520x over previous
#include <cuda_runtime.h>
#include <cstdint>

#define Nn   2048
#define IND  128
#define HIDD 64
#define Ee   32768
#define EPSf 1e-5f
#define NOUT 4096   /* HIDD*HIDD */
#define KX   384    /* expanded K for 3xTF32-as-plain-GEMM */
#define NB2  4224   /* B2 rows: 4096 W1 + 64 Wp2 + 64 zero pad */

// -------- scratch (device globals; no allocation allowed) --------
__device__ __align__(256) float g_p1[Nn * NOUT];     // relu(h@W1+b1)
__device__ __align__(256) float g_p2[Nn * HIDD];     // relu(h@Wp2+bp2)
__device__ __align__(256) uint32_t g_A2[Nn * KX];    // [m][k']: Ah|Ah|Al (tf32 bits)
__device__ __align__(256) uint32_t g_B2[NB2 * KX];   // [n][k']: Bh|Bl|Bh (tf32 bits)
__device__ __align__(256) float g_u[Nn * IND];       // src-half conv of LN(local)
__device__ __align__(256) float g_v[Nn * IND];       // dst-half conv of LN(local)
__device__ __align__(256) uint32_t g_wghi[HIDD * HIDD];  // tf32 split of Wg
__device__ __align__(256) uint32_t g_wglo[HIDD * HIDD];
__device__ __align__(256) uint4 g_w2pk[HIDD * 64];   // packed tf32 split of W2
__device__ __align__(256) float g_C[HIDD];
__device__ int g_off[Nn + 1];
__device__ int g_eidx[Ee];

// ================= tf32 helpers =================
__device__ __forceinline__ uint32_t f2tf(float x) {
    uint32_t r;
    asm("cvt.rna.tf32.f32 %0, %1;" : "=r"(r) : "f"(x));
    return r;
}
__device__ __forceinline__ void mma_tf32(float* d, const uint32_t* a, const uint32_t* b) {
    asm volatile(
        "mma.sync.aligned.m16n8k8.row.col.f32.tf32.tf32.f32 "
        "{%0,%1,%2,%3}, {%4,%5,%6,%7}, {%8,%9}, {%0,%1,%2,%3};"
        : "+f"(d[0]), "+f"(d[1]), "+f"(d[2]), "+f"(d[3])
        : "r"(a[0]), "r"(a[1]), "r"(a[2]), "r"(a[3]), "r"(b[0]), "r"(b[1]));
}

// ================= fused bucketing =================
__global__ __launch_bounds__(1024) void k_bucket(const int* __restrict__ src) {
    __shared__ int cnt[Nn];
    __shared__ int warpsum[32];
    int t = threadIdx.x;
    cnt[t] = 0;
    cnt[t + 1024] = 0;
    __syncthreads();
    for (int e = t; e < Ee; e += 1024) atomicAdd(&cnt[src[e]], 1);
    __syncthreads();

    int c0 = cnt[2 * t], c1 = cnt[2 * t + 1];
    int s = c0 + c1;
    int lane = t & 31, warp = t >> 5;
    int v = s;
#pragma unroll
    for (int o = 1; o < 32; o <<= 1) {
        int u = __shfl_up_sync(0xffffffffu, v, o);
        if (lane >= o) v += u;
    }
    if (lane == 31) warpsum[warp] = v;
    __syncthreads();
    if (warp == 0) {
        int w = warpsum[lane];
#pragma unroll
        for (int o = 1; o < 32; o <<= 1) {
            int u = __shfl_up_sync(0xffffffffu, w, o);
            if (lane >= o) w += u;
        }
        warpsum[lane] = w;
    }
    __syncthreads();
    int excl = v - s + (warp ? warpsum[warp - 1] : 0);
    g_off[2 * t] = excl;
    g_off[2 * t + 1] = excl + c0;
    if (t == 1023) g_off[Nn] = excl + s;
    __syncthreads();
    cnt[2 * t] = excl;
    cnt[2 * t + 1] = excl + c0;
    __syncthreads();
    for (int e = t; e < Ee; e += 1024) {
        int p = atomicAdd(&cnt[src[e]], 1);
        g_eidx[p] = e;
    }
}

// ================= prep: Wg split + C + packed W2 =================
__global__ void k_prep(const float* __restrict__ W3,
                       const float* __restrict__ b3,
                       const float* __restrict__ bng_g,
                       const float* __restrict__ bng_b,
                       const float* __restrict__ bnG_g,
                       const float* __restrict__ bnG_b,
                       const float* __restrict__ W2) {
    int idx = blockIdx.x * blockDim.x + threadIdx.x;
    float rs = rsqrtf(1.f + EPSf);
    if (idx < 4096) {
        int d = idx >> 6, dp = idx & 63;
        float wg = (bng_g[d] * rs) * W3[idx] * (bnG_g[dp] * rs);
        uint32_t hi = f2tf(wg);
        g_wghi[idx] = hi;
        g_wglo[idx] = f2tf(wg - __uint_as_float(hi));
    } else if (idx < 4096 + 1024) {
        int j = idx - 4096;
        int n = j & 63, kb = j >> 6;
        uint32_t hi[8], lo[8];
#pragma unroll
        for (int jj = 0; jj < 8; jj++) {
            float x = W2[(kb * 8 + jj) * HIDD + n];
            hi[jj] = f2tf(x);
            lo[jj] = f2tf(x - __uint_as_float(hi[jj]));
        }
#pragma unroll
        for (int tq = 0; tq < 4; tq++)
            g_w2pk[n * 64 + kb * 4 + tq] = make_uint4(hi[tq], hi[tq + 4], lo[tq], lo[tq + 4]);
    } else if (idx < 4096 + 1024 + 64) {
        int dp = idx - 5120;
        float s = 0.f;
        for (int d = 0; d < 64; d++) s += bng_b[d] * W3[d * 64 + dp];
        g_C[dp] = (s + b3[dp]) * (bnG_g[dp] * rs) + bnG_b[dp];
    }
}

// ================= cvtA: h -> A2 = [Ah|Ah|Al] =================
__global__ __launch_bounds__(256) void k_cvtA(const float* __restrict__ h) {
    int idx = blockIdx.x * 256 + threadIdx.x;    // 2048*32
    int row = idx >> 5, k4 = (idx & 31) * 4;
    float4 v = *(const float4*)&h[row * IND + k4];
    uint4 hi, lo;
    hi.x = f2tf(v.x); lo.x = f2tf(v.x - __uint_as_float(hi.x));
    hi.y = f2tf(v.y); lo.y = f2tf(v.y - __uint_as_float(hi.y));
    hi.z = f2tf(v.z); lo.z = f2tf(v.z - __uint_as_float(hi.z));
    hi.w = f2tf(v.w); lo.w = f2tf(v.w - __uint_as_float(hi.w));
    uint32_t* base = &g_A2[row * KX];
    *(uint4*)&base[k4] = hi;
    *(uint4*)&base[128 + k4] = hi;
    *(uint4*)&base[256 + k4] = lo;
}

// ================= cvtB: W1/Wp2 -> B2 = [Bh|Bl|Bh] (n-major, via smem transpose) =================
__global__ __launch_bounds__(256) void k_cvtB(const float* __restrict__ W1,
                                              const float* __restrict__ Wp2) {
    __shared__ float Ws[IND][68];
    int tid = threadIdx.x;
    int b = blockIdx.x;            // 0..65
    int n0 = b * 64;

#pragma unroll
    for (int it = 0; it < 32; it++) {
        int idx = tid + it * 256;  // 8192 = 128k x 64n
        int k = idx >> 6, n = idx & 63;
        float val;
        if (b < 64)      val = W1[k * NOUT + n0 + n];
        else if (b == 64) val = Wp2[k * HIDD + n];
        else              val = 0.f;
        Ws[k][n] = val;
    }
    __syncthreads();

#pragma unroll
    for (int it = 0; it < 8; it++) {
        int idx = tid + it * 256;  // 2048 = 64n x 32 k4-groups
        int n = idx >> 5, k4 = (idx & 31) * 4;
        uint4 hi, lo;
        float x0 = Ws[k4 + 0][n], x1 = Ws[k4 + 1][n], x2 = Ws[k4 + 2][n], x3 = Ws[k4 + 3][n];
        hi.x = f2tf(x0); lo.x = f2tf(x0 - __uint_as_float(hi.x));
        hi.y = f2tf(x1); lo.y = f2tf(x1 - __uint_as_float(hi.y));
        hi.z = f2tf(x2); lo.z = f2tf(x2 - __uint_as_float(hi.z));
        hi.w = f2tf(x3); lo.w = f2tf(x3 - __uint_as_float(hi.w));
        uint32_t* base = &g_B2[(n0 + n) * KX];
        *(uint4*)&base[k4] = hi;
        *(uint4*)&base[128 + k4] = lo;
        *(uint4*)&base[256 + k4] = hi;
    }
}

// ================= p1 GEMM: plain tf32 mma, K=384, zero cvt =================
#define AST 36
#define P1M_SMEM (2 * 128 * AST * 4)   /* 36864 */

__global__ __launch_bounds__(256) void k_p1mm(const float* __restrict__ b1,
                                              const float* __restrict__ bp2) {
    extern __shared__ uint32_t smu[];
    uint32_t* As = smu;                // [128][AST]
    uint32_t* Bs = smu + 128 * AST;    // [128][AST]

    int tid = threadIdx.x;
    int wid = tid >> 5, lane = tid & 31;
    int g = lane >> 2, t = lane & 3;
    int warp_m = (wid >> 2) * 64;
    int warp_n = (wid & 3) * 32;
    int bx = blockIdx.x;
    int row0 = blockIdx.y * 128;
    int col0 = bx * 128;
    bool p2tile = (bx == 32);

    float acc[4][4][4];
#pragma unroll
    for (int mi = 0; mi < 4; mi++)
#pragma unroll
        for (int ni = 0; ni < 4; ni++)
#pragma unroll
            for (int r = 0; r < 4; r++) acc[mi][ni][r] = 0.f;

    for (int kc = 0; kc < KX; kc += 32) {
#pragma unroll
        for (int it = 0; it < 4; it++) {
            int idx = tid + it * 256;      // 1024: m x k4
            int m = idx >> 3, k4 = (idx & 7) * 4;
            uint4 v = *(const uint4*)&g_A2[(row0 + m) * KX + kc + k4];
            *(uint4*)&As[m * AST + k4] = v;
        }
#pragma unroll
        for (int it = 0; it < 4; it++) {
            int idx = tid + it * 256;
            int n = idx >> 3, k4 = (idx & 7) * 4;
            uint4 v = *(const uint4*)&g_B2[(col0 + n) * KX + kc + k4];
            *(uint4*)&Bs[n * AST + k4] = v;
        }
        __syncthreads();

#pragma unroll
        for (int ks = 0; ks < 32; ks += 8) {
            uint32_t a[4][4], b[4][2];
#pragma unroll
            for (int mi = 0; mi < 4; mi++) {
                int r = warp_m + mi * 16 + g;
                a[mi][0] = As[r * AST + ks + t];
                a[mi][1] = As[(r + 8) * AST + ks + t];
                a[mi][2] = As[r * AST + ks + t + 4];
                a[mi][3] = As[(r + 8) * AST + ks + t + 4];
            }
#pragma unroll
            for (int ni = 0; ni < 4; ni++) {
                int n = warp_n + ni * 8 + g;
                b[ni][0] = Bs[n * AST + ks + t];
                b[ni][1] = Bs[n * AST + ks + t + 4];
            }
#pragma unroll
            for (int mi = 0; mi < 4; mi++)
#pragma unroll
                for (int ni = 0; ni < 4; ni++)
                    mma_tf32(acc[mi][ni], a[mi], b[ni]);
        }
        __syncthreads();
    }

    if (!p2tile) {
#pragma unroll
        for (int mi = 0; mi < 4; mi++) {
            int r = row0 + warp_m + mi * 16 + g;
#pragma unroll
            for (int ni = 0; ni < 4; ni++) {
                int c = col0 + warp_n + ni * 8 + t * 2;
                float2 bb = *(const float2*)&b1[c];
                float2 o0, o1;
                o0.x = fmaxf(acc[mi][ni][0] + bb.x, 0.f);
                o0.y = fmaxf(acc[mi][ni][1] + bb.y, 0.f);
                o1.x = fmaxf(acc[mi][ni][2] + bb.x, 0.f);
                o1.y = fmaxf(acc[mi][ni][3] + bb.y, 0.f);
                *(float2*)&g_p1[(size_t)r * NOUT + c] = o0;
                *(float2*)&g_p1[(size_t)(r + 8) * NOUT + c] = o1;
            }
        }
    } else {
#pragma unroll
        for (int mi = 0; mi < 4; mi++) {
            int r = row0 + warp_m + mi * 16 + g;
#pragma unroll
            for (int ni = 0; ni < 4; ni++) {
                int c = warp_n + ni * 8 + t * 2;
                if (c < HIDD) {
                    float2 bb = *(const float2*)&bp2[c];
                    float2 o0, o1;
                    o0.x = fmaxf(acc[mi][ni][0] + bb.x, 0.f);
                    o0.y = fmaxf(acc[mi][ni][1] + bb.y, 0.f);
                    o1.x = fmaxf(acc[mi][ni][2] + bb.x, 0.f);
                    o1.y = fmaxf(acc[mi][ni][3] + bb.y, 0.f);
                    *(float2*)&g_p2[r * HIDD + c] = o0;
                    *(float2*)&g_p2[(r + 8) * HIDD + c] = o1;
                }
            }
        }
    }
}

// ================= node prep: LN(local[i]) -> u[i], v[i] =================
__global__ __launch_bounds__(256) void k_nodeprep(const float* __restrict__ local,
                                                  const float* __restrict__ ln_w,
                                                  const float* __restrict__ ln_b,
                                                  const float* __restrict__ conv_w) {
    __shared__ float lns[2][IND + 2];
    __shared__ float2 red[2][4];
    int tid = threadIdx.x;
    int grp = tid >> 7, t = tid & 127;
    int node = blockIdx.x * 2 + grp;
    int lane = t & 31, warp = t >> 5;

    float x = local[node * IND + t];
    float2 v = make_float2(x, x * x);
#pragma unroll
    for (int o = 16; o; o >>= 1) {
        v.x += __shfl_down_sync(0xffffffffu, v.x, o);
        v.y += __shfl_down_sync(0xffffffffu, v.y, o);
    }
    if (lane == 0) red[grp][warp] = v;
    if (t == 0) { lns[grp][0] = 0.f; lns[grp][IND + 1] = 0.f; }
    __syncthreads();
    float2 tot = red[grp][0];
    tot.x += red[grp][1].x + red[grp][2].x + red[grp][3].x;
    tot.y += red[grp][1].y + red[grp][2].y + red[grp][3].y;
    float mu = tot.x * (1.f / IND);
    float var = tot.y * (1.f / IND) - mu * mu;
    float ln = (x - mu) * rsqrtf(var + EPSf) * ln_w[t] + ln_b[t];
    lns[grp][t + 1] = ln;
    __syncthreads();
    float l0 = lns[grp][t], l1 = lns[grp][t + 1], l2 = lns[grp][t + 2];
    g_u[node * IND + t] = conv_w[0] * l0 + conv_w[1] * l1 + conv_w[2] * l2;
    g_v[node * IND + t] = conv_w[3] * l0 + conv_w[4] * l1 + conv_w[5] * l2;
}

// ================= local branch v3: fully packed, zero cvt in mainloop =================
#define TPK_STR 68
#define L3_SMEM ((32 * TPK_STR + 64 * TPK_STR) * 16)

__global__ __launch_bounds__(256) void k_local3(const int* __restrict__ src,
                                                const int* __restrict__ dst,
                                                const float* __restrict__ conv_b,
                                                const float* __restrict__ b2,
                                                const float* __restrict__ bnL_g,
                                                const float* __restrict__ bnL_b,
                                                const float* __restrict__ ein,
                                                float* __restrict__ out) {
    extern __shared__ char smraw[];
    uint4* Tpk = (uint4*)smraw;
    uint4* W2p = (uint4*)(smraw + 32 * TPK_STR * 16);

    int tid = threadIdx.x;
    int e0 = blockIdx.x * 32;
    float cb = conv_b[0];

#pragma unroll
    for (int it = 0; it < 2; it++) {
        int idx = tid + it * 256;
        int e = idx >> 4, kb = idx & 15;
        int se = src[e0 + e], de = dst[e0 + e];
        const float4* pu = (const float4*)&g_u[se * IND + kb * 8];
        const float4* pv = (const float4*)&g_v[de * IND + kb * 8];
        float4 u0 = pu[0], u1 = pu[1], v0 = pv[0], v1 = pv[1];
        float xv[8] = {u0.x + v0.x + cb, u0.y + v0.y + cb, u0.z + v0.z + cb, u0.w + v0.w + cb,
                       u1.x + v1.x + cb, u1.y + v1.y + cb, u1.z + v1.z + cb, u1.w + v1.w + cb};
        uint32_t hi[8], lo[8];
#pragma unroll
        for (int j = 0; j < 8; j++) {
            float x = fmaxf(xv[j], 0.f);
            hi[j] = f2tf(x);
            lo[j] = f2tf(x - __uint_as_float(hi[j]));
        }
#pragma unroll
        for (int tq = 0; tq < 4; tq++)
            Tpk[e * TPK_STR + kb * 4 + tq] = make_uint4(hi[tq], hi[tq + 4], lo[tq], lo[tq + 4]);
    }
#pragma unroll
    for (int it = 0; it < 16; it++) {
        int idx = tid + it * 256;
        int n = idx >> 6, c = idx & 63;
        W2p[n * TPK_STR + c] = g_w2pk[n * 64 + c];
    }
    __syncthreads();

    int wid = tid >> 5, lane = tid & 31;
    int g = lane >> 2, t = lane & 3;
    int m0 = (wid & 1) * 16;
    int n0 = (wid >> 1) * 16;
    int r = m0 + g;

    float acc[2][4];
#pragma unroll
    for (int ni = 0; ni < 2; ni++)
#pragma unroll
        for (int q = 0; q < 4; q++) acc[ni][q] = 0.f;

#pragma unroll 4
    for (int kb = 0; kb < 16; kb++) {
        uint4 a0 = Tpk[r * TPK_STR + kb * 4 + t];
        uint4 a1 = Tpk[(r + 8) * TPK_STR + kb * 4 + t];
        uint32_t ah[4] = {a0.x, a1.x, a0.y, a1.y};
        uint32_t al[4] = {a0.z, a1.z, a0.w, a1.w};
#pragma unroll
        for (int ni = 0; ni < 2; ni++) {
            uint4 bfr = W2p[(n0 + ni * 8 + g) * TPK_STR + kb * 4 + t];
            uint32_t bh2[2] = {bfr.x, bfr.y};
            uint32_t bl2[2] = {bfr.z, bfr.w};
            mma_tf32(acc[ni], ah, bh2);
            mma_tf32(acc[ni], ah, bl2);
            mma_tf32(acc[ni], al, bh2);
        }
    }

    float rs = rsqrtf(1.f + EPSf);
    int ea = e0 + m0 + g, eb = ea + 8;
#pragma unroll
    for (int ni = 0; ni < 2; ni++) {
        int c = n0 + ni * 8 + t * 2;
        float2 bb = *(const float2*)&b2[c];
        float2 gg = *(const float2*)&bnL_g[c];
        float2 bL = *(const float2*)&bnL_b[c];
        float2 ia = *(const float2*)&ein[ea * HIDD + c];
        float2 ib = *(const float2*)&ein[eb * HIDD + c];
        float2 oa, ob;
        oa.x = fmaxf((acc[ni][0] + bb.x) * (gg.x * rs) + bL.x, 0.f) + ia.x;
        oa.y = fmaxf((acc[ni][1] + bb.y) * (gg.y * rs) + bL.y, 0.f) + ia.y;
        ob.x = fmaxf((acc[ni][2] + bb.x) * (gg.x * rs) + bL.x, 0.f) + ib.x;
        ob.y = fmaxf((acc[ni][3] + bb.y) * (gg.y * rs) + bL.y, 0.f) + ib.y;
        *(float2*)&out[ea * HIDD + c] = oa;
        *(float2*)&out[eb * HIDD + c] = ob;
    }
}

// ================= global branch fused =================
#define GA_STR 68
#define ECAP 64
#define GO_AS  0
#define GO_BHI (64 * GA_STR * 4)
#define GO_BLO (GO_BHI + 64 * 72 * 4)
#define GO_P2  (GO_BLO + 64 * 72 * 4)
#define GO_EIX (GO_P2 + ECAP * 64 * 4)
#define G2_SMEM (GO_EIX + ECAP * 4)

__global__ __launch_bounds__(256) void k_global2(const int* __restrict__ dst,
                                                 float* __restrict__ out) {
    extern __shared__ char smraw[];
    float* As = (float*)(smraw + GO_AS);
    float* Gs = As;
    uint32_t* Bhi = (uint32_t*)(smraw + GO_BHI);
    uint32_t* Blo = (uint32_t*)(smraw + GO_BLO);
    float* p2buf = (float*)(smraw + GO_P2);
    int* eixs = (int*)(smraw + GO_EIX);

    int node = blockIdx.x;
    int tid = threadIdx.x;
    int beg = g_off[node], end = g_off[node + 1];
    if (beg == end) return;

    int ec = min(end - beg, ECAP);
    for (int idx = tid; idx < ec * 64; idx += 256) {
        int ei = idx >> 6, d2 = idx & 63;
        int e = g_eidx[beg + ei];
        if (d2 == 0) eixs[ei] = e;
        p2buf[idx] = g_p2[dst[e] * HIDD + d2];
    }

    const float* p1row = &g_p1[(size_t)node * NOUT];
#pragma unroll
    for (int it = 0; it < 16; it++) {
        int idx = tid + it * 256;
        int d = idx >> 6, k = idx & 63;
        As[k * GA_STR + d] = p1row[idx];
    }
#pragma unroll
    for (int it = 0; it < 16; it++) {
        int idx = tid + it * 256;
        int d = idx >> 6, dp = idx & 63;
        Bhi[d * 72 + dp] = g_wghi[idx];
        Blo[d * 72 + dp] = g_wglo[idx];
    }
    __syncthreads();

    int wid = tid >> 5, lane = tid & 31;
    int g = lane >> 2, t = lane & 3;
    int m0 = (wid & 3) * 16;
    int n0 = (wid >> 2) * 32;

    float acc[4][4];
#pragma unroll
    for (int ni = 0; ni < 4; ni++)
#pragma unroll
        for (int r = 0; r < 4; r++) acc[ni][r] = 0.f;

#pragma unroll
    for (int ks = 0; ks < 64; ks += 8) {
        uint32_t ahi[4], alo[4], bh[4][2], bl[4][2];
        int r = m0 + g;
        float a0 = As[r * GA_STR + ks + t];
        float a1 = As[(r + 8) * GA_STR + ks + t];
        float a2 = As[r * GA_STR + ks + t + 4];
        float a3 = As[(r + 8) * GA_STR + ks + t + 4];
        ahi[0] = f2tf(a0); alo[0] = f2tf(a0 - __uint_as_float(ahi[0]));
        ahi[1] = f2tf(a1); alo[1] = f2tf(a1 - __uint_as_float(ahi[1]));
        ahi[2] = f2tf(a2); alo[2] = f2tf(a2 - __uint_as_float(ahi[2]));
        ahi[3] = f2tf(a3); alo[3] = f2tf(a3 - __uint_as_float(ahi[3]));
#pragma unroll
        for (int ni = 0; ni < 4; ni++) {
            int n = n0 + ni * 8 + g;
            bh[ni][0] = Bhi[(ks + t) * 72 + n];
            bh[ni][1] = Bhi[(ks + t + 4) * 72 + n];
            bl[ni][0] = Blo[(ks + t) * 72 + n];
            bl[ni][1] = Blo[(ks + t + 4) * 72 + n];
        }
#pragma unroll
        for (int ni = 0; ni < 4; ni++) {
            mma_tf32(acc[ni], ahi, bh[ni]);
            mma_tf32(acc[ni], ahi, bl[ni]);
            mma_tf32(acc[ni], alo, bh[ni]);
        }
    }
    __syncthreads();

    int m = m0 + g;
#pragma unroll
    for (int ni = 0; ni < 4; ni++) {
        int n = n0 + ni * 8 + t * 2;
        Gs[m * 65 + n] = acc[ni][0];
        Gs[m * 65 + n + 1] = acc[ni][1];
        Gs[(m + 8) * 65 + n] = acc[ni][2];
        Gs[(m + 8) * 65 + n + 1] = acc[ni][3];
    }
    __syncthreads();

    int d = tid & 63, grp = tid >> 6;
    float Gr[64];
#pragma unroll
    for (int k = 0; k < 64; k++) Gr[k] = Gs[k * 65 + d];
    float Cd = g_C[d];

    int base = beg;
    while (true) {
        for (int e = grp; e < ec; e += 4) {
            const float4* p = (const float4*)&p2buf[e * 64];
            float a2 = 0.f;
#pragma unroll
            for (int k4 = 0; k4 < 16; k4++) {
                float4 v = p[k4];
                a2 += Gr[k4 * 4 + 0] * v.x + Gr[k4 * 4 + 1] * v.y
                    + Gr[k4 * 4 + 2] * v.z + Gr[k4 * 4 + 3] * v.w;
            }
            int eg = eixs[e];
            out[eg * HIDD + d] += fmaxf(a2 + Cd, 0.f);
        }
        base += ec;
        if (base >= end) break;
        __syncthreads();
        ec = min(end - base, ECAP);
        for (int idx = tid; idx < ec * 64; idx += 256) {
            int ei = idx >> 6, d2 = idx & 63;
            int e = g_eidx[base + ei];
            if (d2 == 0) eixs[ei] = e;
            p2buf[idx] = g_p2[dst[e] * HIDD + d2];
        }
        __syncthreads();
    }
}

// ================= launch =================
extern "C" void kernel_launch(void* const* d_in, const int* in_sizes, int n_in,
                              void* d_out, int out_size) {
    const float* h      = (const float*)d_in[0];
    const float* local_ = (const float*)d_in[1];
    const float* ein    = (const float*)d_in[2];
    const int*   src    = (const int*)d_in[3];
    const int*   dst    = (const int*)d_in[4];
    const float* ln_w   = (const float*)d_in[5];
    const float* ln_b   = (const float*)d_in[6];
    const float* conv_w = (const float*)d_in[7];
    const float* conv_b = (const float*)d_in[8];
    const float* W1     = (const float*)d_in[9];
    const float* b1     = (const float*)d_in[10];
    const float* Wp2    = (const float*)d_in[11];
    const float* bp2    = (const float*)d_in[12];
    const float* W2     = (const float*)d_in[13];
    const float* b2     = (const float*)d_in[14];
    const float* W3     = (const float*)d_in[15];
    const float* b3     = (const float*)d_in[16];
    const float* bng_g  = (const float*)d_in[17];
    const float* bng_b  = (const float*)d_in[18];
    const float* bnG_g  = (const float*)d_in[19];
    const float* bnG_b  = (const float*)d_in[20];
    const float* bnL_g  = (const float*)d_in[21];
    const float* bnL_b  = (const float*)d_in[22];
    float* out = (float*)d_out;

    static int smem_set = 0;
    if (!smem_set) {
        cudaFuncSetAttribute(k_p1mm, cudaFuncAttributeMaxDynamicSharedMemorySize, P1M_SMEM);
        cudaFuncSetAttribute(k_local3, cudaFuncAttributeMaxDynamicSharedMemorySize, L3_SMEM);
        cudaFuncSetAttribute(k_global2, cudaFuncAttributeMaxDynamicSharedMemorySize, G2_SMEM);
        smem_set = 1;
    }

    k_bucket<<<1, 1024>>>(src);
    k_cvtA<<<(Nn * 32) / 256, 256>>>(h);
    k_cvtB<<<66, 256>>>(W1, Wp2);
    k_p1mm<<<dim3(33, Nn / 128), 256, P1M_SMEM>>>(b1, bp2);   // 4th -> profiled
    k_prep<<<21, 256>>>(W3, b3, bng_g, bng_b, bnG_g, bnG_b, W2);
    k_nodeprep<<<Nn / 2, 256>>>(local_, ln_w, ln_b, conv_w);
    k_local3<<<Ee / 32, 256, L3_SMEM>>>(src, dst, conv_b, b2, bnL_g, bnL_b, ein, out);
    k_global2<<<Nn, 256, G2_SMEM>>>(dst, out);
}

// round 12
// speedup vs baseline: 1.0739x; 1.0208x over previous
#include <cuda_runtime.h>
#include <cstdint>

#define Nn   2048
#define IND  128
#define HIDD 64
#define Ee   32768
#define EPSf 1e-5f
#define NOUT 4096   /* HIDD*HIDD */
#define KX   384    /* expanded K for 3xTF32-as-plain-GEMM */
#define NB2  4224   /* B2 rows: 4096 W1 + 64 Wp2 + 64 zero pad */

// -------- scratch (device globals; no allocation allowed) --------
__device__ __align__(256) float g_p1[Nn * NOUT];     // relu(h@W1+b1)
__device__ __align__(256) float g_p2[Nn * HIDD];     // relu(h@Wp2+bp2)
__device__ __align__(256) uint32_t g_A2[Nn * KX];    // [m][k']: Ah|Ah|Al (tf32 bits)
__device__ __align__(256) uint32_t g_B2[NB2 * KX];   // [n][k']: Bh|Bl|Bh (tf32 bits)
__device__ __align__(256) float g_u[Nn * IND];       // src-half conv of LN(local)
__device__ __align__(256) float g_v[Nn * IND];       // dst-half conv of LN(local)
__device__ __align__(256) uint32_t g_wghi[HIDD * HIDD];  // tf32 split of Wg
__device__ __align__(256) uint32_t g_wglo[HIDD * HIDD];
__device__ __align__(256) uint4 g_w2pk[HIDD * 64];   // packed tf32 split of W2
__device__ __align__(256) float g_C[HIDD];
__device__ int g_off[Nn + 1];
__device__ int g_eidx[Ee];

// ================= tf32 / async helpers =================
__device__ __forceinline__ uint32_t f2tf(float x) {
    uint32_t r;
    asm("cvt.rna.tf32.f32 %0, %1;" : "=r"(r) : "f"(x));
    return r;
}
__device__ __forceinline__ void mma_tf32(float* d, const uint32_t* a, const uint32_t* b) {
    asm volatile(
        "mma.sync.aligned.m16n8k8.row.col.f32.tf32.tf32.f32 "
        "{%0,%1,%2,%3}, {%4,%5,%6,%7}, {%8,%9}, {%0,%1,%2,%3};"
        : "+f"(d[0]), "+f"(d[1]), "+f"(d[2]), "+f"(d[3])
        : "r"(a[0]), "r"(a[1]), "r"(a[2]), "r"(a[3]), "r"(b[0]), "r"(b[1]));
}
__device__ __forceinline__ uint32_t smem_u32(const void* p) {
    uint32_t a;
    asm("{ .reg .u64 t; cvta.to.shared.u64 t, %1; cvt.u32.u64 %0, t; }" : "=r"(a) : "l"(p));
    return a;
}
__device__ __forceinline__ void cp_async16(uint32_t saddr, const void* gptr) {
    asm volatile("cp.async.cg.shared.global [%0], [%1], 16;" :: "r"(saddr), "l"(gptr));
}
#define CP_COMMIT() asm volatile("cp.async.commit_group;" ::: "memory")
#define CP_WAIT(n)  asm volatile("cp.async.wait_group %0;" :: "n"(n) : "memory")

// ================= fused bucketing =================
__global__ __launch_bounds__(1024) void k_bucket(const int* __restrict__ src) {
    __shared__ int cnt[Nn];
    __shared__ int warpsum[32];
    int t = threadIdx.x;
    cnt[t] = 0;
    cnt[t + 1024] = 0;
    __syncthreads();
    for (int e = t; e < Ee; e += 1024) atomicAdd(&cnt[src[e]], 1);
    __syncthreads();

    int c0 = cnt[2 * t], c1 = cnt[2 * t + 1];
    int s = c0 + c1;
    int lane = t & 31, warp = t >> 5;
    int v = s;
#pragma unroll
    for (int o = 1; o < 32; o <<= 1) {
        int u = __shfl_up_sync(0xffffffffu, v, o);
        if (lane >= o) v += u;
    }
    if (lane == 31) warpsum[warp] = v;
    __syncthreads();
    if (warp == 0) {
        int w = warpsum[lane];
#pragma unroll
        for (int o = 1; o < 32; o <<= 1) {
            int u = __shfl_up_sync(0xffffffffu, w, o);
            if (lane >= o) w += u;
        }
        warpsum[lane] = w;
    }
    __syncthreads();
    int excl = v - s + (warp ? warpsum[warp - 1] : 0);
    g_off[2 * t] = excl;
    g_off[2 * t + 1] = excl + c0;
    if (t == 1023) g_off[Nn] = excl + s;
    __syncthreads();
    cnt[2 * t] = excl;
    cnt[2 * t + 1] = excl + c0;
    __syncthreads();
    for (int e = t; e < Ee; e += 1024) {
        int p = atomicAdd(&cnt[src[e]], 1);
        g_eidx[p] = e;
    }
}

// ================= prep: Wg split + C + packed W2 =================
__global__ void k_prep(const float* __restrict__ W3,
                       const float* __restrict__ b3,
                       const float* __restrict__ bng_g,
                       const float* __restrict__ bng_b,
                       const float* __restrict__ bnG_g,
                       const float* __restrict__ bnG_b,
                       const float* __restrict__ W2) {
    int idx = blockIdx.x * blockDim.x + threadIdx.x;
    float rs = rsqrtf(1.f + EPSf);
    if (idx < 4096) {
        int d = idx >> 6, dp = idx & 63;
        float wg = (bng_g[d] * rs) * W3[idx] * (bnG_g[dp] * rs);
        uint32_t hi = f2tf(wg);
        g_wghi[idx] = hi;
        g_wglo[idx] = f2tf(wg - __uint_as_float(hi));
    } else if (idx < 4096 + 1024) {
        int j = idx - 4096;
        int n = j & 63, kb = j >> 6;
        uint32_t hi[8], lo[8];
#pragma unroll
        for (int jj = 0; jj < 8; jj++) {
            float x = W2[(kb * 8 + jj) * HIDD + n];
            hi[jj] = f2tf(x);
            lo[jj] = f2tf(x - __uint_as_float(hi[jj]));
        }
#pragma unroll
        for (int tq = 0; tq < 4; tq++)
            g_w2pk[n * 64 + kb * 4 + tq] = make_uint4(hi[tq], hi[tq + 4], lo[tq], lo[tq + 4]);
    } else if (idx < 4096 + 1024 + 64) {
        int dp = idx - 5120;
        float s = 0.f;
        for (int d = 0; d < 64; d++) s += bng_b[d] * W3[d * 64 + dp];
        g_C[dp] = (s + b3[dp]) * (bnG_g[dp] * rs) + bnG_b[dp];
    }
}

// ================= cvtA: h -> A2 = [Ah|Ah|Al] =================
__global__ __launch_bounds__(256) void k_cvtA(const float* __restrict__ h) {
    int idx = blockIdx.x * 256 + threadIdx.x;
    int row = idx >> 5, k4 = (idx & 31) * 4;
    float4 v = *(const float4*)&h[row * IND + k4];
    uint4 hi, lo;
    hi.x = f2tf(v.x); lo.x = f2tf(v.x - __uint_as_float(hi.x));
    hi.y = f2tf(v.y); lo.y = f2tf(v.y - __uint_as_float(hi.y));
    hi.z = f2tf(v.z); lo.z = f2tf(v.z - __uint_as_float(hi.z));
    hi.w = f2tf(v.w); lo.w = f2tf(v.w - __uint_as_float(hi.w));
    uint32_t* base = &g_A2[row * KX];
    *(uint4*)&base[k4] = hi;
    *(uint4*)&base[128 + k4] = hi;
    *(uint4*)&base[256 + k4] = lo;
}

// ================= cvtB: W1/Wp2 -> B2 = [Bh|Bl|Bh] =================
__global__ __launch_bounds__(256) void k_cvtB(const float* __restrict__ W1,
                                              const float* __restrict__ Wp2) {
    __shared__ float Ws[IND][68];
    int tid = threadIdx.x;
    int b = blockIdx.x;
    int n0 = b * 64;

#pragma unroll
    for (int it = 0; it < 32; it++) {
        int idx = tid + it * 256;
        int k = idx >> 6, n = idx & 63;
        float val;
        if (b < 64)      val = W1[k * NOUT + n0 + n];
        else if (b == 64) val = Wp2[k * HIDD + n];
        else              val = 0.f;
        Ws[k][n] = val;
    }
    __syncthreads();

#pragma unroll
    for (int it = 0; it < 8; it++) {
        int idx = tid + it * 256;
        int n = idx >> 5, k4 = (idx & 31) * 4;
        uint4 hi, lo;
        float x0 = Ws[k4 + 0][n], x1 = Ws[k4 + 1][n], x2 = Ws[k4 + 2][n], x3 = Ws[k4 + 3][n];
        hi.x = f2tf(x0); lo.x = f2tf(x0 - __uint_as_float(hi.x));
        hi.y = f2tf(x1); lo.y = f2tf(x1 - __uint_as_float(hi.y));
        hi.z = f2tf(x2); lo.z = f2tf(x2 - __uint_as_float(hi.z));
        hi.w = f2tf(x3); lo.w = f2tf(x3 - __uint_as_float(hi.w));
        uint32_t* base = &g_B2[(n0 + n) * KX];
        *(uint4*)&base[k4] = hi;
        *(uint4*)&base[128 + k4] = lo;
        *(uint4*)&base[256 + k4] = hi;
    }
}

// ================= p1 GEMM: plain tf32 mma, cp.async 2-stage pipeline =================
#define AST 36
#define STAGE_U32 (2 * 128 * AST)            /* A + B per stage, uint32 */
#define P1M_SMEM (2 * STAGE_U32 * 4)         /* 73728 */
#define NCHUNK (KX / 32)                     /* 12 */

__global__ __launch_bounds__(256) void k_p1mm(const float* __restrict__ b1,
                                              const float* __restrict__ bp2) {
    extern __shared__ uint32_t smu[];
    int tid = threadIdx.x;
    int wid = tid >> 5, lane = tid & 31;
    int g = lane >> 2, t = lane & 3;
    int warp_m = (wid >> 2) * 64;
    int warp_n = (wid & 3) * 32;
    int bx = blockIdx.x;
    int row0 = blockIdx.y * 128;
    int col0 = bx * 128;
    bool p2tile = (bx == 32);

    uint32_t sb = smem_u32(smu);

    // per-thread load coordinates (4 uint4 for A, 4 for B per stage)
    int lm[4], lk4[4];
#pragma unroll
    for (int it = 0; it < 4; it++) {
        int idx = tid + it * 256;
        lm[it] = idx >> 3;
        lk4[it] = (idx & 7) * 4;
    }

    float acc[4][4][4];
#pragma unroll
    for (int mi = 0; mi < 4; mi++)
#pragma unroll
        for (int ni = 0; ni < 4; ni++)
#pragma unroll
            for (int r = 0; r < 4; r++) acc[mi][ni][r] = 0.f;

    // ---- prologue: issue stage 0 ----
    {
        uint32_t s0 = sb;
#pragma unroll
        for (int it = 0; it < 4; it++)
            cp_async16(s0 + (lm[it] * AST + lk4[it]) * 4, &g_A2[(row0 + lm[it]) * KX + lk4[it]]);
#pragma unroll
        for (int it = 0; it < 4; it++)
            cp_async16(s0 + (128 * AST + lm[it] * AST + lk4[it]) * 4, &g_B2[(size_t)(col0 + lm[it]) * KX + lk4[it]]);
        CP_COMMIT();
    }

    for (int c = 0; c < NCHUNK; c++) {
        if (c + 1 < NCHUNK) {
            int kc = (c + 1) * 32;
            uint32_t s1 = sb + ((c + 1) & 1) * STAGE_U32 * 4;
#pragma unroll
            for (int it = 0; it < 4; it++)
                cp_async16(s1 + (lm[it] * AST + lk4[it]) * 4, &g_A2[(row0 + lm[it]) * KX + kc + lk4[it]]);
#pragma unroll
            for (int it = 0; it < 4; it++)
                cp_async16(s1 + (128 * AST + lm[it] * AST + lk4[it]) * 4, &g_B2[(size_t)(col0 + lm[it]) * KX + kc + lk4[it]]);
            CP_COMMIT();
            CP_WAIT(1);
        } else {
            CP_WAIT(0);
        }
        __syncthreads();

        uint32_t* As = smu + (c & 1) * STAGE_U32;
        uint32_t* Bs = As + 128 * AST;
#pragma unroll
        for (int ks = 0; ks < 32; ks += 8) {
            uint32_t a[4][4], b[4][2];
#pragma unroll
            for (int mi = 0; mi < 4; mi++) {
                int r = warp_m + mi * 16 + g;
                a[mi][0] = As[r * AST + ks + t];
                a[mi][1] = As[(r + 8) * AST + ks + t];
                a[mi][2] = As[r * AST + ks + t + 4];
                a[mi][3] = As[(r + 8) * AST + ks + t + 4];
            }
#pragma unroll
            for (int ni = 0; ni < 4; ni++) {
                int n = warp_n + ni * 8 + g;
                b[ni][0] = Bs[n * AST + ks + t];
                b[ni][1] = Bs[n * AST + ks + t + 4];
            }
#pragma unroll
            for (int mi = 0; mi < 4; mi++)
#pragma unroll
                for (int ni = 0; ni < 4; ni++)
                    mma_tf32(acc[mi][ni], a[mi], b[ni]);
        }
        __syncthreads();
    }

    if (!p2tile) {
#pragma unroll
        for (int mi = 0; mi < 4; mi++) {
            int r = row0 + warp_m + mi * 16 + g;
#pragma unroll
            for (int ni = 0; ni < 4; ni++) {
                int c = col0 + warp_n + ni * 8 + t * 2;
                float2 bb = *(const float2*)&b1[c];
                float2 o0, o1;
                o0.x = fmaxf(acc[mi][ni][0] + bb.x, 0.f);
                o0.y = fmaxf(acc[mi][ni][1] + bb.y, 0.f);
                o1.x = fmaxf(acc[mi][ni][2] + bb.x, 0.f);
                o1.y = fmaxf(acc[mi][ni][3] + bb.y, 0.f);
                *(float2*)&g_p1[(size_t)r * NOUT + c] = o0;
                *(float2*)&g_p1[(size_t)(r + 8) * NOUT + c] = o1;
            }
        }
    } else {
#pragma unroll
        for (int mi = 0; mi < 4; mi++) {
            int r = row0 + warp_m + mi * 16 + g;
#pragma unroll
            for (int ni = 0; ni < 4; ni++) {
                int c = warp_n + ni * 8 + t * 2;
                if (c < HIDD) {
                    float2 bb = *(const float2*)&bp2[c];
                    float2 o0, o1;
                    o0.x = fmaxf(acc[mi][ni][0] + bb.x, 0.f);
                    o0.y = fmaxf(acc[mi][ni][1] + bb.y, 0.f);
                    o1.x = fmaxf(acc[mi][ni][2] + bb.x, 0.f);
                    o1.y = fmaxf(acc[mi][ni][3] + bb.y, 0.f);
                    *(float2*)&g_p2[r * HIDD + c] = o0;
                    *(float2*)&g_p2[(r + 8) * HIDD + c] = o1;
                }
            }
        }
    }
}

// ================= node prep: LN(local[i]) -> u[i], v[i] =================
__global__ __launch_bounds__(256) void k_nodeprep(const float* __restrict__ local,
                                                  const float* __restrict__ ln_w,
                                                  const float* __restrict__ ln_b,
                                                  const float* __restrict__ conv_w) {
    __shared__ float lns[2][IND + 2];
    __shared__ float2 red[2][4];
    int tid = threadIdx.x;
    int grp = tid >> 7, t = tid & 127;
    int node = blockIdx.x * 2 + grp;
    int lane = t & 31, warp = t >> 5;

    float x = local[node * IND + t];
    float2 v = make_float2(x, x * x);
#pragma unroll
    for (int o = 16; o; o >>= 1) {
        v.x += __shfl_down_sync(0xffffffffu, v.x, o);
        v.y += __shfl_down_sync(0xffffffffu, v.y, o);
    }
    if (lane == 0) red[grp][warp] = v;
    if (t == 0) { lns[grp][0] = 0.f; lns[grp][IND + 1] = 0.f; }
    __syncthreads();
    float2 tot = red[grp][0];
    tot.x += red[grp][1].x + red[grp][2].x + red[grp][3].x;
    tot.y += red[grp][1].y + red[grp][2].y + red[grp][3].y;
    float mu = tot.x * (1.f / IND);
    float var = tot.y * (1.f / IND) - mu * mu;
    float ln = (x - mu) * rsqrtf(var + EPSf) * ln_w[t] + ln_b[t];
    lns[grp][t + 1] = ln;
    __syncthreads();
    float l0 = lns[grp][t], l1 = lns[grp][t + 1], l2 = lns[grp][t + 2];
    g_u[node * IND + t] = conv_w[0] * l0 + conv_w[1] * l1 + conv_w[2] * l2;
    g_v[node * IND + t] = conv_w[3] * l0 + conv_w[4] * l1 + conv_w[5] * l2;
}

// ================= local branch v3: fully packed, zero cvt in mainloop =================
#define TPK_STR 68
#define L3_SMEM ((32 * TPK_STR + 64 * TPK_STR) * 16)

__global__ __launch_bounds__(256) void k_local3(const int* __restrict__ src,
                                                const int* __restrict__ dst,
                                                const float* __restrict__ conv_b,
                                                const float* __restrict__ b2,
                                                const float* __restrict__ bnL_g,
                                                const float* __restrict__ bnL_b,
                                                const float* __restrict__ ein,
                                                float* __restrict__ out) {
    extern __shared__ char smraw[];
    uint4* Tpk = (uint4*)smraw;
    uint4* W2p = (uint4*)(smraw + 32 * TPK_STR * 16);

    int tid = threadIdx.x;
    int e0 = blockIdx.x * 32;
    float cb = conv_b[0];

#pragma unroll
    for (int it = 0; it < 2; it++) {
        int idx = tid + it * 256;
        int e = idx >> 4, kb = idx & 15;
        int se = src[e0 + e], de = dst[e0 + e];
        const float4* pu = (const float4*)&g_u[se * IND + kb * 8];
        const float4* pv = (const float4*)&g_v[de * IND + kb * 8];
        float4 u0 = pu[0], u1 = pu[1], v0 = pv[0], v1 = pv[1];
        float xv[8] = {u0.x + v0.x + cb, u0.y + v0.y + cb, u0.z + v0.z + cb, u0.w + v0.w + cb,
                       u1.x + v1.x + cb, u1.y + v1.y + cb, u1.z + v1.z + cb, u1.w + v1.w + cb};
        uint32_t hi[8], lo[8];
#pragma unroll
        for (int j = 0; j < 8; j++) {
            float x = fmaxf(xv[j], 0.f);
            hi[j] = f2tf(x);
            lo[j] = f2tf(x - __uint_as_float(hi[j]));
        }
#pragma unroll
        for (int tq = 0; tq < 4; tq++)
            Tpk[e * TPK_STR + kb * 4 + tq] = make_uint4(hi[tq], hi[tq + 4], lo[tq], lo[tq + 4]);
    }
#pragma unroll
    for (int it = 0; it < 16; it++) {
        int idx = tid + it * 256;
        int n = idx >> 6, c = idx & 63;
        W2p[n * TPK_STR + c] = g_w2pk[n * 64 + c];
    }
    __syncthreads();

    int wid = tid >> 5, lane = tid & 31;
    int g = lane >> 2, t = lane & 3;
    int m0 = (wid & 1) * 16;
    int n0 = (wid >> 1) * 16;
    int r = m0 + g;

    float acc[2][4];
#pragma unroll
    for (int ni = 0; ni < 2; ni++)
#pragma unroll
        for (int q = 0; q < 4; q++) acc[ni][q] = 0.f;

#pragma unroll 4
    for (int kb = 0; kb < 16; kb++) {
        uint4 a0 = Tpk[r * TPK_STR + kb * 4 + t];
        uint4 a1 = Tpk[(r + 8) * TPK_STR + kb * 4 + t];
        uint32_t ah[4] = {a0.x, a1.x, a0.y, a1.y};
        uint32_t al[4] = {a0.z, a1.z, a0.w, a1.w};
#pragma unroll
        for (int ni = 0; ni < 2; ni++) {
            uint4 bfr = W2p[(n0 + ni * 8 + g) * TPK_STR + kb * 4 + t];
            uint32_t bh2[2] = {bfr.x, bfr.y};
            uint32_t bl2[2] = {bfr.z, bfr.w};
            mma_tf32(acc[ni], ah, bh2);
            mma_tf32(acc[ni], ah, bl2);
            mma_tf32(acc[ni], al, bh2);
        }
    }

    float rs = rsqrtf(1.f + EPSf);
    int ea = e0 + m0 + g, eb = ea + 8;
#pragma unroll
    for (int ni = 0; ni < 2; ni++) {
        int c = n0 + ni * 8 + t * 2;
        float2 bb = *(const float2*)&b2[c];
        float2 gg = *(const float2*)&bnL_g[c];
        float2 bL = *(const float2*)&bnL_b[c];
        float2 ia = *(const float2*)&ein[ea * HIDD + c];
        float2 ib = *(const float2*)&ein[eb * HIDD + c];
        float2 oa, ob;
        oa.x = fmaxf((acc[ni][0] + bb.x) * (gg.x * rs) + bL.x, 0.f) + ia.x;
        oa.y = fmaxf((acc[ni][1] + bb.y) * (gg.y * rs) + bL.y, 0.f) + ia.y;
        ob.x = fmaxf((acc[ni][2] + bb.x) * (gg.x * rs) + bL.x, 0.f) + ib.x;
        ob.y = fmaxf((acc[ni][3] + bb.y) * (gg.y * rs) + bL.y, 0.f) + ib.y;
        *(float2*)&out[ea * HIDD + c] = oa;
        *(float2*)&out[eb * HIDD + c] = ob;
    }
}

// ================= global branch fused =================
#define GA_STR 68
#define ECAP 64
#define GO_AS  0
#define GO_BHI (64 * GA_STR * 4)
#define GO_BLO (GO_BHI + 64 * 72 * 4)
#define GO_P2  (GO_BLO + 64 * 72 * 4)
#define GO_EIX (GO_P2 + ECAP * 64 * 4)
#define G2_SMEM (GO_EIX + ECAP * 4)

__global__ __launch_bounds__(256) void k_global2(const int* __restrict__ dst,
                                                 float* __restrict__ out) {
    extern __shared__ char smraw[];
    float* As = (float*)(smraw + GO_AS);
    float* Gs = As;
    uint32_t* Bhi = (uint32_t*)(smraw + GO_BHI);
    uint32_t* Blo = (uint32_t*)(smraw + GO_BLO);
    float* p2buf = (float*)(smraw + GO_P2);
    int* eixs = (int*)(smraw + GO_EIX);

    int node = blockIdx.x;
    int tid = threadIdx.x;
    int beg = g_off[node], end = g_off[node + 1];
    if (beg == end) return;

    int ec = min(end - beg, ECAP);
    for (int idx = tid; idx < ec * 64; idx += 256) {
        int ei = idx >> 6, d2 = idx & 63;
        int e = g_eidx[beg + ei];
        if (d2 == 0) eixs[ei] = e;
        p2buf[idx] = g_p2[dst[e] * HIDD + d2];
    }

    const float* p1row = &g_p1[(size_t)node * NOUT];
#pragma unroll
    for (int it = 0; it < 16; it++) {
        int idx = tid + it * 256;
        int d = idx >> 6, k = idx & 63;
        As[k * GA_STR + d] = p1row[idx];
    }
#pragma unroll
    for (int it = 0; it < 16; it++) {
        int idx = tid + it * 256;
        int d = idx >> 6, dp = idx & 63;
        Bhi[d * 72 + dp] = g_wghi[idx];
        Blo[d * 72 + dp] = g_wglo[idx];
    }
    __syncthreads();

    int wid = tid >> 5, lane = tid & 31;
    int g = lane >> 2, t = lane & 3;
    int m0 = (wid & 3) * 16;
    int n0 = (wid >> 2) * 32;

    float acc[4][4];
#pragma unroll
    for (int ni = 0; ni < 4; ni++)
#pragma unroll
        for (int r = 0; r < 4; r++) acc[ni][r] = 0.f;

#pragma unroll
    for (int ks = 0; ks < 64; ks += 8) {
        uint32_t ahi[4], alo[4], bh[4][2], bl[4][2];
        int r = m0 + g;
        float a0 = As[r * GA_STR + ks + t];
        float a1 = As[(r + 8) * GA_STR + ks + t];
        float a2 = As[r * GA_STR + ks + t + 4];
        float a3 = As[(r + 8) * GA_STR + ks + t + 4];
        ahi[0] = f2tf(a0); alo[0] = f2tf(a0 - __uint_as_float(ahi[0]));
        ahi[1] = f2tf(a1); alo[1] = f2tf(a1 - __uint_as_float(ahi[1]));
        ahi[2] = f2tf(a2); alo[2] = f2tf(a2 - __uint_as_float(ahi[2]));
        ahi[3] = f2tf(a3); alo[3] = f2tf(a3 - __uint_as_float(ahi[3]));
#pragma unroll
        for (int ni = 0; ni < 4; ni++) {
            int n = n0 + ni * 8 + g;
            bh[ni][0] = Bhi[(ks + t) * 72 + n];
            bh[ni][1] = Bhi[(ks + t + 4) * 72 + n];
            bl[ni][0] = Blo[(ks + t) * 72 + n];
            bl[ni][1] = Blo[(ks + t + 4) * 72 + n];
        }
#pragma unroll
        for (int ni = 0; ni < 4; ni++) {
            mma_tf32(acc[ni], ahi, bh[ni]);
            mma_tf32(acc[ni], ahi, bl[ni]);
            mma_tf32(acc[ni], alo, bh[ni]);
        }
    }
    __syncthreads();

    int m = m0 + g;
#pragma unroll
    for (int ni = 0; ni < 4; ni++) {
        int n = n0 + ni * 8 + t * 2;
        Gs[m * 65 + n] = acc[ni][0];
        Gs[m * 65 + n + 1] = acc[ni][1];
        Gs[(m + 8) * 65 + n] = acc[ni][2];
        Gs[(m + 8) * 65 + n + 1] = acc[ni][3];
    }
    __syncthreads();

    int d = tid & 63, grp = tid >> 6;
    float Gr[64];
#pragma unroll
    for (int k = 0; k < 64; k++) Gr[k] = Gs[k * 65 + d];
    float Cd = g_C[d];

    int base = beg;
    while (true) {
        for (int e = grp; e < ec; e += 4) {
            const float4* p = (const float4*)&p2buf[e * 64];
            float a2 = 0.f;
#pragma unroll
            for (int k4 = 0; k4 < 16; k4++) {
                float4 v = p[k4];
                a2 += Gr[k4 * 4 + 0] * v.x + Gr[k4 * 4 + 1] * v.y
                    + Gr[k4 * 4 + 2] * v.z + Gr[k4 * 4 + 3] * v.w;
            }
            int eg = eixs[e];
            out[eg * HIDD + d] += fmaxf(a2 + Cd, 0.f);
        }
        base += ec;
        if (base >= end) break;
        __syncthreads();
        ec = min(end - base, ECAP);
        for (int idx = tid; idx < ec * 64; idx += 256) {
            int ei = idx >> 6, d2 = idx & 63;
            int e = g_eidx[base + ei];
            if (d2 == 0) eixs[ei] = e;
            p2buf[idx] = g_p2[dst[e] * HIDD + d2];
        }
        __syncthreads();
    }
}

// ================= launch =================
extern "C" void kernel_launch(void* const* d_in, const int* in_sizes, int n_in,
                              void* d_out, int out_size) {
    const float* h      = (const float*)d_in[0];
    const float* local_ = (const float*)d_in[1];
    const float* ein    = (const float*)d_in[2];
    const int*   src    = (const int*)d_in[3];
    const int*   dst    = (const int*)d_in[4];
    const float* ln_w   = (const float*)d_in[5];
    const float* ln_b   = (const float*)d_in[6];
    const float* conv_w = (const float*)d_in[7];
    const float* conv_b = (const float*)d_in[8];
    const float* W1     = (const float*)d_in[9];
    const float* b1     = (const float*)d_in[10];
    const float* Wp2    = (const float*)d_in[11];
    const float* bp2    = (const float*)d_in[12];
    const float* W2     = (const float*)d_in[13];
    const float* b2     = (const float*)d_in[14];
    const float* W3     = (const float*)d_in[15];
    const float* b3     = (const float*)d_in[16];
    const float* bng_g  = (const float*)d_in[17];
    const float* bng_b  = (const float*)d_in[18];
    const float* bnG_g  = (const float*)d_in[19];
    const float* bnG_b  = (const float*)d_in[20];
    const float* bnL_g  = (const float*)d_in[21];
    const float* bnL_b  = (const float*)d_in[22];
    float* out = (float*)d_out;

    static int smem_set = 0;
    if (!smem_set) {
        cudaFuncSetAttribute(k_p1mm, cudaFuncAttributeMaxDynamicSharedMemorySize, P1M_SMEM);
        cudaFuncSetAttribute(k_local3, cudaFuncAttributeMaxDynamicSharedMemorySize, L3_SMEM);
        cudaFuncSetAttribute(k_global2, cudaFuncAttributeMaxDynamicSharedMemorySize, G2_SMEM);
        smem_set = 1;
    }

    k_bucket<<<1, 1024>>>(src);
    k_cvtA<<<(Nn * 32) / 256, 256>>>(h);
    k_cvtB<<<66, 256>>>(W1, Wp2);
    k_p1mm<<<dim3(33, Nn / 128), 256, P1M_SMEM>>>(b1, bp2);   // 4th -> profiled
    k_prep<<<21, 256>>>(W3, b3, bng_g, bng_b, bnG_g, bnG_b, W2);
    k_nodeprep<<<Nn / 2, 256>>>(local_, ln_w, ln_b, conv_w);
    k_local3<<<Ee / 32, 256, L3_SMEM>>>(src, dst, conv_b, b2, bnL_g, bnL_b, ein, out);
    k_global2<<<Nn, 256, G2_SMEM>>>(dst, out);
}

// round 13
// speedup vs baseline: 1.1179x; 1.0410x over previous
#include <cuda_runtime.h>
#include <cstdint>

#define Nn   2048
#define IND  128
#define HIDD 64
#define Ee   32768
#define EPSf 1e-5f
#define NOUT 4096   /* HIDD*HIDD */
#define NB2  4224   /* B rows: 4096 W1 + 64 Wp2 + 64 zero pad */

// -------- scratch (device globals; no allocation allowed) --------
__device__ __align__(256) float g_p1[Nn * NOUT];     // relu(h@W1+b1)
__device__ __align__(256) float g_p2[Nn * HIDD];     // relu(h@Wp2+bp2)
__device__ __align__(256) uint4 g_A2p[Nn * 64];      // frag-packed tf32 split of h
__device__ __align__(256) uint4 g_B2p[NB2 * 64];     // frag-packed tf32 split of W1/Wp2 (n-major)
__device__ __align__(256) float g_u[Nn * IND];       // src-half conv of LN(local)
__device__ __align__(256) float g_v[Nn * IND];       // dst-half conv of LN(local)
__device__ __align__(256) uint32_t g_wghi[HIDD * HIDD];  // tf32 split of Wg
__device__ __align__(256) uint32_t g_wglo[HIDD * HIDD];
__device__ __align__(256) uint4 g_w2pk[HIDD * 64];   // packed tf32 split of W2
__device__ __align__(256) float g_C[HIDD];
__device__ int g_off[Nn + 1];
__device__ int g_eidx[Ee];

// ================= tf32 / async helpers =================
__device__ __forceinline__ uint32_t f2tf(float x) {
    uint32_t r;
    asm("cvt.rna.tf32.f32 %0, %1;" : "=r"(r) : "f"(x));
    return r;
}
__device__ __forceinline__ void mma_tf32(float* d, const uint32_t* a, const uint32_t* b) {
    asm volatile(
        "mma.sync.aligned.m16n8k8.row.col.f32.tf32.tf32.f32 "
        "{%0,%1,%2,%3}, {%4,%5,%6,%7}, {%8,%9}, {%0,%1,%2,%3};"
        : "+f"(d[0]), "+f"(d[1]), "+f"(d[2]), "+f"(d[3])
        : "r"(a[0]), "r"(a[1]), "r"(a[2]), "r"(a[3]), "r"(b[0]), "r"(b[1]));
}
__device__ __forceinline__ uint32_t smem_u32(const void* p) {
    uint32_t a;
    asm("{ .reg .u64 t; cvta.to.shared.u64 t, %1; cvt.u32.u64 %0, t; }" : "=r"(a) : "l"(p));
    return a;
}
__device__ __forceinline__ void cp_async16(uint32_t saddr, const void* gptr) {
    asm volatile("cp.async.cg.shared.global [%0], [%1], 16;" :: "r"(saddr), "l"(gptr));
}
#define CP_COMMIT() asm volatile("cp.async.commit_group;" ::: "memory")
#define CP_WAIT(n)  asm volatile("cp.async.wait_group %0;" :: "n"(n) : "memory")

// ================= fused bucketing =================
__global__ __launch_bounds__(1024) void k_bucket(const int* __restrict__ src) {
    __shared__ int cnt[Nn];
    __shared__ int warpsum[32];
    int t = threadIdx.x;
    cnt[t] = 0;
    cnt[t + 1024] = 0;
    __syncthreads();
    for (int e = t; e < Ee; e += 1024) atomicAdd(&cnt[src[e]], 1);
    __syncthreads();

    int c0 = cnt[2 * t], c1 = cnt[2 * t + 1];
    int s = c0 + c1;
    int lane = t & 31, warp = t >> 5;
    int v = s;
#pragma unroll
    for (int o = 1; o < 32; o <<= 1) {
        int u = __shfl_up_sync(0xffffffffu, v, o);
        if (lane >= o) v += u;
    }
    if (lane == 31) warpsum[warp] = v;
    __syncthreads();
    if (warp == 0) {
        int w = warpsum[lane];
#pragma unroll
        for (int o = 1; o < 32; o <<= 1) {
            int u = __shfl_up_sync(0xffffffffu, w, o);
            if (lane >= o) w += u;
        }
        warpsum[lane] = w;
    }
    __syncthreads();
    int excl = v - s + (warp ? warpsum[warp - 1] : 0);
    g_off[2 * t] = excl;
    g_off[2 * t + 1] = excl + c0;
    if (t == 1023) g_off[Nn] = excl + s;
    __syncthreads();
    cnt[2 * t] = excl;
    cnt[2 * t + 1] = excl + c0;
    __syncthreads();
    for (int e = t; e < Ee; e += 1024) {
        int p = atomicAdd(&cnt[src[e]], 1);
        g_eidx[p] = e;
    }
}

// ================= prep: Wg split + C + packed W2 =================
__global__ void k_prep(const float* __restrict__ W3,
                       const float* __restrict__ b3,
                       const float* __restrict__ bng_g,
                       const float* __restrict__ bng_b,
                       const float* __restrict__ bnG_g,
                       const float* __restrict__ bnG_b,
                       const float* __restrict__ W2) {
    int idx = blockIdx.x * blockDim.x + threadIdx.x;
    float rs = rsqrtf(1.f + EPSf);
    if (idx < 4096) {
        int d = idx >> 6, dp = idx & 63;
        float wg = (bng_g[d] * rs) * W3[idx] * (bnG_g[dp] * rs);
        uint32_t hi = f2tf(wg);
        g_wghi[idx] = hi;
        g_wglo[idx] = f2tf(wg - __uint_as_float(hi));
    } else if (idx < 4096 + 1024) {
        int j = idx - 4096;
        int n = j & 63, kb = j >> 6;
        uint32_t hi[8], lo[8];
#pragma unroll
        for (int jj = 0; jj < 8; jj++) {
            float x = W2[(kb * 8 + jj) * HIDD + n];
            hi[jj] = f2tf(x);
            lo[jj] = f2tf(x - __uint_as_float(hi[jj]));
        }
#pragma unroll
        for (int tq = 0; tq < 4; tq++)
            g_w2pk[n * 64 + kb * 4 + tq] = make_uint4(hi[tq], hi[tq + 4], lo[tq], lo[tq + 4]);
    } else if (idx < 4096 + 1024 + 64) {
        int dp = idx - 5120;
        float s = 0.f;
        for (int d = 0; d < 64; d++) s += bng_b[d] * W3[d * 64 + dp];
        g_C[dp] = (s + b3[dp]) * (bnG_g[dp] * rs) + bnG_b[dp];
    }
}

// ================= cvtA: h -> frag-packed tf32 split =================
__global__ __launch_bounds__(256) void k_cvtA(const float* __restrict__ h) {
    int idx = blockIdx.x * 256 + threadIdx.x;    // Nn*16
    int m = idx >> 4, kb = idx & 15;
    const float4* p = (const float4*)&h[m * IND + kb * 8];
    float4 v0 = p[0], v1 = p[1];
    float xv[8] = {v0.x, v0.y, v0.z, v0.w, v1.x, v1.y, v1.z, v1.w};
    uint32_t hi[8], lo[8];
#pragma unroll
    for (int j = 0; j < 8; j++) {
        hi[j] = f2tf(xv[j]);
        lo[j] = f2tf(xv[j] - __uint_as_float(hi[j]));
    }
#pragma unroll
    for (int tq = 0; tq < 4; tq++)
        g_A2p[m * 64 + kb * 4 + tq] = make_uint4(hi[tq], hi[tq + 4], lo[tq], lo[tq + 4]);
}

// ================= cvtB: W1/Wp2 -> frag-packed (n-major, via smem transpose) =================
__global__ __launch_bounds__(256) void k_cvtB(const float* __restrict__ W1,
                                              const float* __restrict__ Wp2) {
    __shared__ float Ws[IND][68];
    int tid = threadIdx.x;
    int b = blockIdx.x;            // 0..65
    int n0 = b * 64;

#pragma unroll
    for (int it = 0; it < 32; it++) {
        int idx = tid + it * 256;
        int k = idx >> 6, n = idx & 63;
        float val;
        if (b < 64)      val = W1[k * NOUT + n0 + n];
        else if (b == 64) val = Wp2[k * HIDD + n];
        else              val = 0.f;
        Ws[k][n] = val;
    }
    __syncthreads();

#pragma unroll
    for (int it = 0; it < 4; it++) {
        int idx = tid + it * 256;  // 1024 = 64n x 16kb
        int n = idx >> 4, kb = idx & 15;
        uint32_t hi[8], lo[8];
#pragma unroll
        for (int j = 0; j < 8; j++) {
            float x = Ws[kb * 8 + j][n];
            hi[j] = f2tf(x);
            lo[j] = f2tf(x - __uint_as_float(hi[j]));
        }
#pragma unroll
        for (int tq = 0; tq < 4; tq++)
            g_B2p[(size_t)(n0 + n) * 64 + kb * 4 + tq] =
                make_uint4(hi[tq], hi[tq + 4], lo[tq], lo[tq + 4]);
    }
}

// ================= p1 GEMM: frag-packed tf32, LDS.128 mainloop, cp.async 2-stage =================
#define BST 12                         /* uint4 row stride (=4 mod 8 -> conflict-free) */
#define STG_U4 (2 * 128 * BST)         /* A+B per stage in uint4 = 3072 */
#define P1M_SMEM (2 * STG_U4 * 16)     /* 98304 */
#define NCHUNK 8                       /* K=128 in chunks of 2 kb (16 k) */

__global__ __launch_bounds__(256) void k_p1mm(const float* __restrict__ b1,
                                              const float* __restrict__ bp2) {
    extern __shared__ uint4 smq[];
    int tid = threadIdx.x;
    int wid = tid >> 5, lane = tid & 31;
    int g = lane >> 2, t = lane & 3;
    int warp_m = (wid >> 2) * 64;
    int warp_n = (wid & 3) * 32;
    int bx = blockIdx.x;
    int row0 = blockIdx.y * 128;
    int col0 = bx * 128;
    bool p2tile = (bx == 32);

    uint32_t sb = smem_u32(smq);

    // per-thread load coords: 4 uint4 for A + 4 for B per chunk
    int lm[4], lq[4];
#pragma unroll
    for (int it = 0; it < 4; it++) {
        int idx = tid + it * 256;      // 1024 = 128m x 8q
        lm[it] = idx >> 3;
        lq[it] = idx & 7;
    }

    float acc[4][4][4];
#pragma unroll
    for (int mi = 0; mi < 4; mi++)
#pragma unroll
        for (int ni = 0; ni < 4; ni++)
#pragma unroll
            for (int r = 0; r < 4; r++) acc[mi][ni][r] = 0.f;

    // prologue: stage 0
#pragma unroll
    for (int it = 0; it < 4; it++)
        cp_async16(sb + (lm[it] * BST + lq[it]) * 16, &g_A2p[(row0 + lm[it]) * 64 + lq[it]]);
#pragma unroll
    for (int it = 0; it < 4; it++)
        cp_async16(sb + (128 * BST + lm[it] * BST + lq[it]) * 16,
                   &g_B2p[(size_t)(col0 + lm[it]) * 64 + lq[it]]);
    CP_COMMIT();

    for (int c = 0; c < NCHUNK; c++) {
        if (c + 1 < NCHUNK) {
            int q0 = (c + 1) * 8;
            uint32_t s1 = sb + ((c + 1) & 1) * STG_U4 * 16;
#pragma unroll
            for (int it = 0; it < 4; it++)
                cp_async16(s1 + (lm[it] * BST + lq[it]) * 16,
                           &g_A2p[(row0 + lm[it]) * 64 + q0 + lq[it]]);
#pragma unroll
            for (int it = 0; it < 4; it++)
                cp_async16(s1 + (128 * BST + lm[it] * BST + lq[it]) * 16,
                           &g_B2p[(size_t)(col0 + lm[it]) * 64 + q0 + lq[it]]);
            CP_COMMIT();
            CP_WAIT(1);
        } else {
            CP_WAIT(0);
        }
        __syncthreads();

        uint4* Ap = smq + (c & 1) * STG_U4;
        uint4* Bp = Ap + 128 * BST;
#pragma unroll
        for (int kb2 = 0; kb2 < 2; kb2++) {
            uint4 afr[4][2], bfr[4];
#pragma unroll
            for (int mi = 0; mi < 4; mi++) {
                int r = warp_m + mi * 16 + g;
                afr[mi][0] = Ap[r * BST + kb2 * 4 + t];
                afr[mi][1] = Ap[(r + 8) * BST + kb2 * 4 + t];
            }
#pragma unroll
            for (int ni = 0; ni < 4; ni++)
                bfr[ni] = Bp[(warp_n + ni * 8 + g) * BST + kb2 * 4 + t];
#pragma unroll
            for (int mi = 0; mi < 4; mi++) {
                uint32_t ah[4] = {afr[mi][0].x, afr[mi][1].x, afr[mi][0].y, afr[mi][1].y};
                uint32_t al[4] = {afr[mi][0].z, afr[mi][1].z, afr[mi][0].w, afr[mi][1].w};
#pragma unroll
                for (int ni = 0; ni < 4; ni++) {
                    uint32_t bh2[2] = {bfr[ni].x, bfr[ni].y};
                    uint32_t bl2[2] = {bfr[ni].z, bfr[ni].w};
                    mma_tf32(acc[mi][ni], ah, bh2);
                    mma_tf32(acc[mi][ni], ah, bl2);
                    mma_tf32(acc[mi][ni], al, bh2);
                }
            }
        }
        __syncthreads();
    }

    if (!p2tile) {
#pragma unroll
        for (int mi = 0; mi < 4; mi++) {
            int r = row0 + warp_m + mi * 16 + g;
#pragma unroll
            for (int ni = 0; ni < 4; ni++) {
                int c = col0 + warp_n + ni * 8 + t * 2;
                float2 bb = *(const float2*)&b1[c];
                float2 o0, o1;
                o0.x = fmaxf(acc[mi][ni][0] + bb.x, 0.f);
                o0.y = fmaxf(acc[mi][ni][1] + bb.y, 0.f);
                o1.x = fmaxf(acc[mi][ni][2] + bb.x, 0.f);
                o1.y = fmaxf(acc[mi][ni][3] + bb.y, 0.f);
                *(float2*)&g_p1[(size_t)r * NOUT + c] = o0;
                *(float2*)&g_p1[(size_t)(r + 8) * NOUT + c] = o1;
            }
        }
    } else {
#pragma unroll
        for (int mi = 0; mi < 4; mi++) {
            int r = row0 + warp_m + mi * 16 + g;
#pragma unroll
            for (int ni = 0; ni < 4; ni++) {
                int c = warp_n + ni * 8 + t * 2;
                if (c < HIDD) {
                    float2 bb = *(const float2*)&bp2[c];
                    float2 o0, o1;
                    o0.x = fmaxf(acc[mi][ni][0] + bb.x, 0.f);
                    o0.y = fmaxf(acc[mi][ni][1] + bb.y, 0.f);
                    o1.x = fmaxf(acc[mi][ni][2] + bb.x, 0.f);
                    o1.y = fmaxf(acc[mi][ni][3] + bb.y, 0.f);
                    *(float2*)&g_p2[r * HIDD + c] = o0;
                    *(float2*)&g_p2[(r + 8) * HIDD + c] = o1;
                }
            }
        }
    }
}

// ================= node prep: LN(local[i]) -> u[i], v[i] =================
__global__ __launch_bounds__(256) void k_nodeprep(const float* __restrict__ local,
                                                  const float* __restrict__ ln_w,
                                                  const float* __restrict__ ln_b,
                                                  const float* __restrict__ conv_w) {
    __shared__ float lns[2][IND + 2];
    __shared__ float2 red[2][4];
    int tid = threadIdx.x;
    int grp = tid >> 7, t = tid & 127;
    int node = blockIdx.x * 2 + grp;
    int lane = t & 31, warp = t >> 5;

    float x = local[node * IND + t];
    float2 v = make_float2(x, x * x);
#pragma unroll
    for (int o = 16; o; o >>= 1) {
        v.x += __shfl_down_sync(0xffffffffu, v.x, o);
        v.y += __shfl_down_sync(0xffffffffu, v.y, o);
    }
    if (lane == 0) red[grp][warp] = v;
    if (t == 0) { lns[grp][0] = 0.f; lns[grp][IND + 1] = 0.f; }
    __syncthreads();
    float2 tot = red[grp][0];
    tot.x += red[grp][1].x + red[grp][2].x + red[grp][3].x;
    tot.y += red[grp][1].y + red[grp][2].y + red[grp][3].y;
    float mu = tot.x * (1.f / IND);
    float var = tot.y * (1.f / IND) - mu * mu;
    float ln = (x - mu) * rsqrtf(var + EPSf) * ln_w[t] + ln_b[t];
    lns[grp][t + 1] = ln;
    __syncthreads();
    float l0 = lns[grp][t], l1 = lns[grp][t + 1], l2 = lns[grp][t + 2];
    g_u[node * IND + t] = conv_w[0] * l0 + conv_w[1] * l1 + conv_w[2] * l2;
    g_v[node * IND + t] = conv_w[3] * l0 + conv_w[4] * l1 + conv_w[5] * l2;
}

// ================= local branch v3: fully packed, zero cvt in mainloop =================
#define TPK_STR 68
#define L3_SMEM ((32 * TPK_STR + 64 * TPK_STR) * 16)

__global__ __launch_bounds__(256) void k_local3(const int* __restrict__ src,
                                                const int* __restrict__ dst,
                                                const float* __restrict__ conv_b,
                                                const float* __restrict__ b2,
                                                const float* __restrict__ bnL_g,
                                                const float* __restrict__ bnL_b,
                                                const float* __restrict__ ein,
                                                float* __restrict__ out) {
    extern __shared__ char smraw[];
    uint4* Tpk = (uint4*)smraw;
    uint4* W2p = (uint4*)(smraw + 32 * TPK_STR * 16);

    int tid = threadIdx.x;
    int e0 = blockIdx.x * 32;
    float cb = conv_b[0];

#pragma unroll
    for (int it = 0; it < 2; it++) {
        int idx = tid + it * 256;
        int e = idx >> 4, kb = idx & 15;
        int se = src[e0 + e], de = dst[e0 + e];
        const float4* pu = (const float4*)&g_u[se * IND + kb * 8];
        const float4* pv = (const float4*)&g_v[de * IND + kb * 8];
        float4 u0 = pu[0], u1 = pu[1], v0 = pv[0], v1 = pv[1];
        float xv[8] = {u0.x + v0.x + cb, u0.y + v0.y + cb, u0.z + v0.z + cb, u0.w + v0.w + cb,
                       u1.x + v1.x + cb, u1.y + v1.y + cb, u1.z + v1.z + cb, u1.w + v1.w + cb};
        uint32_t hi[8], lo[8];
#pragma unroll
        for (int j = 0; j < 8; j++) {
            float x = fmaxf(xv[j], 0.f);
            hi[j] = f2tf(x);
            lo[j] = f2tf(x - __uint_as_float(hi[j]));
        }
#pragma unroll
        for (int tq = 0; tq < 4; tq++)
            Tpk[e * TPK_STR + kb * 4 + tq] = make_uint4(hi[tq], hi[tq + 4], lo[tq], lo[tq + 4]);
    }
#pragma unroll
    for (int it = 0; it < 16; it++) {
        int idx = tid + it * 256;
        int n = idx >> 6, c = idx & 63;
        W2p[n * TPK_STR + c] = g_w2pk[n * 64 + c];
    }
    __syncthreads();

    int wid = tid >> 5, lane = tid & 31;
    int g = lane >> 2, t = lane & 3;
    int m0 = (wid & 1) * 16;
    int n0 = (wid >> 1) * 16;
    int r = m0 + g;

    float acc[2][4];
#pragma unroll
    for (int ni = 0; ni < 2; ni++)
#pragma unroll
        for (int q = 0; q < 4; q++) acc[ni][q] = 0.f;

#pragma unroll 4
    for (int kb = 0; kb < 16; kb++) {
        uint4 a0 = Tpk[r * TPK_STR + kb * 4 + t];
        uint4 a1 = Tpk[(r + 8) * TPK_STR + kb * 4 + t];
        uint32_t ah[4] = {a0.x, a1.x, a0.y, a1.y};
        uint32_t al[4] = {a0.z, a1.z, a0.w, a1.w};
#pragma unroll
        for (int ni = 0; ni < 2; ni++) {
            uint4 bfr = W2p[(n0 + ni * 8 + g) * TPK_STR + kb * 4 + t];
            uint32_t bh2[2] = {bfr.x, bfr.y};
            uint32_t bl2[2] = {bfr.z, bfr.w};
            mma_tf32(acc[ni], ah, bh2);
            mma_tf32(acc[ni], ah, bl2);
            mma_tf32(acc[ni], al, bh2);
        }
    }

    float rs = rsqrtf(1.f + EPSf);
    int ea = e0 + m0 + g, eb = ea + 8;
#pragma unroll
    for (int ni = 0; ni < 2; ni++) {
        int c = n0 + ni * 8 + t * 2;
        float2 bb = *(const float2*)&b2[c];
        float2 gg = *(const float2*)&bnL_g[c];
        float2 bL = *(const float2*)&bnL_b[c];
        float2 ia = *(const float2*)&ein[ea * HIDD + c];
        float2 ib = *(const float2*)&ein[eb * HIDD + c];
        float2 oa, ob;
        oa.x = fmaxf((acc[ni][0] + bb.x) * (gg.x * rs) + bL.x, 0.f) + ia.x;
        oa.y = fmaxf((acc[ni][1] + bb.y) * (gg.y * rs) + bL.y, 0.f) + ia.y;
        ob.x = fmaxf((acc[ni][2] + bb.x) * (gg.x * rs) + bL.x, 0.f) + ib.x;
        ob.y = fmaxf((acc[ni][3] + bb.y) * (gg.y * rs) + bL.y, 0.f) + ib.y;
        *(float2*)&out[ea * HIDD + c] = oa;
        *(float2*)&out[eb * HIDD + c] = ob;
    }
}

// ================= global branch fused =================
#define GA_STR 68
#define ECAP 64
#define GO_AS  0
#define GO_BHI (64 * GA_STR * 4)
#define GO_BLO (GO_BHI + 64 * 72 * 4)
#define GO_P2  (GO_BLO + 64 * 72 * 4)
#define GO_EIX (GO_P2 + ECAP * 64 * 4)
#define G2_SMEM (GO_EIX + ECAP * 4)

__global__ __launch_bounds__(256) void k_global2(const int* __restrict__ dst,
                                                 float* __restrict__ out) {
    extern __shared__ char smraw[];
    float* As = (float*)(smraw + GO_AS);
    float* Gs = As;
    uint32_t* Bhi = (uint32_t*)(smraw + GO_BHI);
    uint32_t* Blo = (uint32_t*)(smraw + GO_BLO);
    float* p2buf = (float*)(smraw + GO_P2);
    int* eixs = (int*)(smraw + GO_EIX);

    int node = blockIdx.x;
    int tid = threadIdx.x;
    int beg = g_off[node], end = g_off[node + 1];
    if (beg == end) return;

    int ec = min(end - beg, ECAP);
    for (int idx = tid; idx < ec * 64; idx += 256) {
        int ei = idx >> 6, d2 = idx & 63;
        int e = g_eidx[beg + ei];
        if (d2 == 0) eixs[ei] = e;
        p2buf[idx] = g_p2[dst[e] * HIDD + d2];
    }

    const float* p1row = &g_p1[(size_t)node * NOUT];
#pragma unroll
    for (int it = 0; it < 16; it++) {
        int idx = tid + it * 256;
        int d = idx >> 6, k = idx & 63;
        As[k * GA_STR + d] = p1row[idx];
    }
#pragma unroll
    for (int it = 0; it < 16; it++) {
        int idx = tid + it * 256;
        int d = idx >> 6, dp = idx & 63;
        Bhi[d * 72 + dp] = g_wghi[idx];
        Blo[d * 72 + dp] = g_wglo[idx];
    }
    __syncthreads();

    int wid = tid >> 5, lane = tid & 31;
    int g = lane >> 2, t = lane & 3;
    int m0 = (wid & 3) * 16;
    int n0 = (wid >> 2) * 32;

    float acc[4][4];
#pragma unroll
    for (int ni = 0; ni < 4; ni++)
#pragma unroll
        for (int r = 0; r < 4; r++) acc[ni][r] = 0.f;

#pragma unroll
    for (int ks = 0; ks < 64; ks += 8) {
        uint32_t ahi[4], alo[4], bh[4][2], bl[4][2];
        int r = m0 + g;
        float a0 = As[r * GA_STR + ks + t];
        float a1 = As[(r + 8) * GA_STR + ks + t];
        float a2 = As[r * GA_STR + ks + t + 4];
        float a3 = As[(r + 8) * GA_STR + ks + t + 4];
        ahi[0] = f2tf(a0); alo[0] = f2tf(a0 - __uint_as_float(ahi[0]));
        ahi[1] = f2tf(a1); alo[1] = f2tf(a1 - __uint_as_float(ahi[1]));
        ahi[2] = f2tf(a2); alo[2] = f2tf(a2 - __uint_as_float(ahi[2]));
        ahi[3] = f2tf(a3); alo[3] = f2tf(a3 - __uint_as_float(ahi[3]));
#pragma unroll
        for (int ni = 0; ni < 4; ni++) {
            int n = n0 + ni * 8 + g;
            bh[ni][0] = Bhi[(ks + t) * 72 + n];
            bh[ni][1] = Bhi[(ks + t + 4) * 72 + n];
            bl[ni][0] = Blo[(ks + t) * 72 + n];
            bl[ni][1] = Blo[(ks + t + 4) * 72 + n];
        }
#pragma unroll
        for (int ni = 0; ni < 4; ni++) {
            mma_tf32(acc[ni], ahi, bh[ni]);
            mma_tf32(acc[ni], ahi, bl[ni]);
            mma_tf32(acc[ni], alo, bh[ni]);
        }
    }
    __syncthreads();

    int m = m0 + g;
#pragma unroll
    for (int ni = 0; ni < 4; ni++) {
        int n = n0 + ni * 8 + t * 2;
        Gs[m * 65 + n] = acc[ni][0];
        Gs[m * 65 + n + 1] = acc[ni][1];
        Gs[(m + 8) * 65 + n] = acc[ni][2];
        Gs[(m + 8) * 65 + n + 1] = acc[ni][3];
    }
    __syncthreads();

    int d = tid & 63, grp = tid >> 6;
    float Gr[64];
#pragma unroll
    for (int k = 0; k < 64; k++) Gr[k] = Gs[k * 65 + d];
    float Cd = g_C[d];

    int base = beg;
    while (true) {
        for (int e = grp; e < ec; e += 4) {
            const float4* p = (const float4*)&p2buf[e * 64];
            float a2 = 0.f;
#pragma unroll
            for (int k4 = 0; k4 < 16; k4++) {
                float4 v = p[k4];
                a2 += Gr[k4 * 4 + 0] * v.x + Gr[k4 * 4 + 1] * v.y
                    + Gr[k4 * 4 + 2] * v.z + Gr[k4 * 4 + 3] * v.w;
            }
            int eg = eixs[e];
            out[eg * HIDD + d] += fmaxf(a2 + Cd, 0.f);
        }
        base += ec;
        if (base >= end) break;
        __syncthreads();
        ec = min(end - base, ECAP);
        for (int idx = tid; idx < ec * 64; idx += 256) {
            int ei = idx >> 6, d2 = idx & 63;
            int e = g_eidx[base + ei];
            if (d2 == 0) eixs[ei] = e;
            p2buf[idx] = g_p2[dst[e] * HIDD + d2];
        }
        __syncthreads();
    }
}

// ================= launch =================
extern "C" void kernel_launch(void* const* d_in, const int* in_sizes, int n_in,
                              void* d_out, int out_size) {
    const float* h      = (const float*)d_in[0];
    const float* local_ = (const float*)d_in[1];
    const float* ein    = (const float*)d_in[2];
    const int*   src    = (const int*)d_in[3];
    const int*   dst    = (const int*)d_in[4];
    const float* ln_w   = (const float*)d_in[5];
    const float* ln_b   = (const float*)d_in[6];
    const float* conv_w = (const float*)d_in[7];
    const float* conv_b = (const float*)d_in[8];
    const float* W1     = (const float*)d_in[9];
    const float* b1     = (const float*)d_in[10];
    const float* Wp2    = (const float*)d_in[11];
    const float* bp2    = (const float*)d_in[12];
    const float* W2     = (const float*)d_in[13];
    const float* b2     = (const float*)d_in[14];
    const float* W3     = (const float*)d_in[15];
    const float* b3     = (const float*)d_in[16];
    const float* bng_g  = (const float*)d_in[17];
    const float* bng_b  = (const float*)d_in[18];
    const float* bnG_g  = (const float*)d_in[19];
    const float* bnG_b  = (const float*)d_in[20];
    const float* bnL_g  = (const float*)d_in[21];
    const float* bnL_b  = (const float*)d_in[22];
    float* out = (float*)d_out;

    static int smem_set = 0;
    if (!smem_set) {
        cudaFuncSetAttribute(k_p1mm, cudaFuncAttributeMaxDynamicSharedMemorySize, P1M_SMEM);
        cudaFuncSetAttribute(k_local3, cudaFuncAttributeMaxDynamicSharedMemorySize, L3_SMEM);
        cudaFuncSetAttribute(k_global2, cudaFuncAttributeMaxDynamicSharedMemorySize, G2_SMEM);
        smem_set = 1;
    }

    k_bucket<<<1, 1024>>>(src);
    k_cvtA<<<(Nn * 16) / 256, 256>>>(h);
    k_cvtB<<<66, 256>>>(W1, Wp2);
    k_p1mm<<<dim3(33, Nn / 128), 256, P1M_SMEM>>>(b1, bp2);   // 4th -> profiled
    k_prep<<<21, 256>>>(W3, b3, bng_g, bng_b, bnG_g, bnG_b, W2);
    k_nodeprep<<<Nn / 2, 256>>>(local_, ln_w, ln_b, conv_w);
    k_local3<<<Ee / 32, 256, L3_SMEM>>>(src, dst, conv_b, b2, bnL_g, bnL_b, ein, out);
    k_global2<<<Nn, 256, G2_SMEM>>>(dst, out);
}

// round 14
// speedup vs baseline: 1.2591x; 1.1263x over previous
#include <cuda_runtime.h>
#include <cstdint>

#define Nn   2048
#define IND  128
#define HIDD 64
#define Ee   32768
#define EPSf 1e-5f
#define NOUT 4096   /* HIDD*HIDD */
#define NB2  4224   /* B rows: 4096 W1 + 64 Wp2 + 64 zero pad */

// -------- scratch (device globals; no allocation allowed) --------
__device__ __align__(256) float g_p1[Nn * NOUT];     // relu(h@W1+b1)
__device__ __align__(256) float g_p2[Nn * HIDD];     // relu(h@Wp2+bp2)
__device__ __align__(256) uint4 g_A2p[Nn * 64];      // frag-packed tf32 split of h
__device__ __align__(256) uint4 g_B2p[NB2 * 64];     // frag-packed tf32 split of W1/Wp2 (n-major)
__device__ __align__(256) float g_u[Nn * IND];       // src-half conv of LN(local)
__device__ __align__(256) float g_v[Nn * IND];       // dst-half conv of LN(local)
__device__ __align__(256) uint32_t g_wghi[HIDD * HIDD];  // tf32 split of Wg
__device__ __align__(256) uint32_t g_wglo[HIDD * HIDD];
__device__ __align__(256) uint4 g_w2pk[HIDD * 64];   // packed tf32 split of W2
__device__ __align__(256) float g_C[HIDD];
__device__ int g_off[Nn + 1];
__device__ int g_eidx[Ee];

// ================= tf32 / async helpers =================
__device__ __forceinline__ uint32_t f2tf(float x) {
    uint32_t r;
    asm("cvt.rna.tf32.f32 %0, %1;" : "=r"(r) : "f"(x));
    return r;
}
__device__ __forceinline__ void mma_tf32(float* d, const uint32_t* a, const uint32_t* b) {
    asm volatile(
        "mma.sync.aligned.m16n8k8.row.col.f32.tf32.tf32.f32 "
        "{%0,%1,%2,%3}, {%4,%5,%6,%7}, {%8,%9}, {%0,%1,%2,%3};"
        : "+f"(d[0]), "+f"(d[1]), "+f"(d[2]), "+f"(d[3])
        : "r"(a[0]), "r"(a[1]), "r"(a[2]), "r"(a[3]), "r"(b[0]), "r"(b[1]));
}
__device__ __forceinline__ uint32_t smem_u32(const void* p) {
    uint32_t a;
    asm("{ .reg .u64 t; cvta.to.shared.u64 t, %1; cvt.u32.u64 %0, t; }" : "=r"(a) : "l"(p));
    return a;
}
__device__ __forceinline__ void cp_async16(uint32_t saddr, const void* gptr) {
    asm volatile("cp.async.cg.shared.global [%0], [%1], 16;" :: "r"(saddr), "l"(gptr));
}
#define CP_COMMIT() asm volatile("cp.async.commit_group;" ::: "memory")
#define CP_WAIT(n)  asm volatile("cp.async.wait_group %0;" :: "n"(n) : "memory")

// ================= k_setup: all prep work in ONE launch =================
// blocks [0,64): cvtA   [64,130): cvtB   [130,141): prep
// blocks [141,653): nodeprep (4 nodes each)   block 653: bucket
__global__ __launch_bounds__(512) void k_setup(
    const float* __restrict__ h, const float* __restrict__ W1,
    const float* __restrict__ Wp2,
    const float* __restrict__ W3, const float* __restrict__ b3,
    const float* __restrict__ bng_g, const float* __restrict__ bng_b,
    const float* __restrict__ bnG_g, const float* __restrict__ bnG_b,
    const float* __restrict__ W2,
    const float* __restrict__ local, const float* __restrict__ ln_w,
    const float* __restrict__ ln_b, const float* __restrict__ conv_w,
    const int* __restrict__ src) {
    __shared__ __align__(16) char smraw[36864];
    int bx = blockIdx.x;
    int t = threadIdx.x;
    float rs = rsqrtf(1.f + EPSf);

    if (bx < 64) {
        // ---- cvtA: h -> frag-packed tf32 split ----
        int idx = bx * 512 + t;                  // Nn*16 = 32768
        int m = idx >> 4, kb = idx & 15;
        const float4* p = (const float4*)&h[m * IND + kb * 8];
        float4 v0 = p[0], v1 = p[1];
        float xv[8] = {v0.x, v0.y, v0.z, v0.w, v1.x, v1.y, v1.z, v1.w};
        uint32_t hi[8], lo[8];
#pragma unroll
        for (int j = 0; j < 8; j++) {
            hi[j] = f2tf(xv[j]);
            lo[j] = f2tf(xv[j] - __uint_as_float(hi[j]));
        }
#pragma unroll
        for (int tq = 0; tq < 4; tq++)
            g_A2p[m * 64 + kb * 4 + tq] = make_uint4(hi[tq], hi[tq + 4], lo[tq], lo[tq + 4]);
    } else if (bx < 130) {
        // ---- cvtB: W1/Wp2 -> frag-packed (n-major, via smem transpose) ----
        float (*Ws)[68] = (float(*)[68])smraw;
        int b = bx - 64;                         // 0..65
        int n0 = b * 64;
#pragma unroll
        for (int it = 0; it < 16; it++) {
            int idx = t + it * 512;              // 8192
            int k = idx >> 6, n = idx & 63;
            float val;
            if (b < 64)       val = W1[k * NOUT + n0 + n];
            else if (b == 64) val = Wp2[k * HIDD + n];
            else              val = 0.f;
            Ws[k][n] = val;
        }
        __syncthreads();
#pragma unroll
        for (int it = 0; it < 2; it++) {
            int idx = t + it * 512;              // 1024 = 64n x 16kb
            int n = idx >> 4, kb = idx & 15;
            uint32_t hi[8], lo[8];
#pragma unroll
            for (int j = 0; j < 8; j++) {
                float x = Ws[kb * 8 + j][n];
                hi[j] = f2tf(x);
                lo[j] = f2tf(x - __uint_as_float(hi[j]));
            }
#pragma unroll
            for (int tq = 0; tq < 4; tq++)
                g_B2p[(size_t)(n0 + n) * 64 + kb * 4 + tq] =
                    make_uint4(hi[tq], hi[tq + 4], lo[tq], lo[tq + 4]);
        }
    } else if (bx < 141) {
        // ---- prep: Wg split + packed W2 + C ----
        int idx = (bx - 130) * 512 + t;
        if (idx < 4096) {
            int d = idx >> 6, dp = idx & 63;
            float wg = (bng_g[d] * rs) * W3[idx] * (bnG_g[dp] * rs);
            uint32_t hi = f2tf(wg);
            g_wghi[idx] = hi;
            g_wglo[idx] = f2tf(wg - __uint_as_float(hi));
        } else if (idx < 4096 + 1024) {
            int j = idx - 4096;
            int n = j & 63, kb = j >> 6;
            uint32_t hi[8], lo[8];
#pragma unroll
            for (int jj = 0; jj < 8; jj++) {
                float x = W2[(kb * 8 + jj) * HIDD + n];
                hi[jj] = f2tf(x);
                lo[jj] = f2tf(x - __uint_as_float(hi[jj]));
            }
#pragma unroll
            for (int tq = 0; tq < 4; tq++)
                g_w2pk[n * 64 + kb * 4 + tq] = make_uint4(hi[tq], hi[tq + 4], lo[tq], lo[tq + 4]);
        } else if (idx < 4096 + 1024 + 64) {
            int dp = idx - 5120;
            float s = 0.f;
            for (int d = 0; d < 64; d++) s += bng_b[d] * W3[d * 64 + dp];
            g_C[dp] = (s + b3[dp]) * (bnG_g[dp] * rs) + bnG_b[dp];
        }
    } else if (bx < 653) {
        // ---- nodeprep: LN(local) -> u, v (4 nodes per block) ----
        float (*lns)[IND + 2] = (float(*)[IND + 2])smraw;       // 4*130*4 = 2080
        float2 (*red)[4] = (float2(*)[4])(smraw + 2112);        // 4*4*8 = 128
        int grp = t >> 7, tt = t & 127;
        int node = (bx - 141) * 4 + grp;
        int lane = tt & 31, warp = tt >> 5;

        float x = local[node * IND + tt];
        float2 v = make_float2(x, x * x);
#pragma unroll
        for (int o = 16; o; o >>= 1) {
            v.x += __shfl_down_sync(0xffffffffu, v.x, o);
            v.y += __shfl_down_sync(0xffffffffu, v.y, o);
        }
        if (lane == 0) red[grp][warp] = v;
        if (tt == 0) { lns[grp][0] = 0.f; lns[grp][IND + 1] = 0.f; }
        __syncthreads();
        float2 tot = red[grp][0];
        tot.x += red[grp][1].x + red[grp][2].x + red[grp][3].x;
        tot.y += red[grp][1].y + red[grp][2].y + red[grp][3].y;
        float mu = tot.x * (1.f / IND);
        float var = tot.y * (1.f / IND) - mu * mu;
        float ln = (x - mu) * rsqrtf(var + EPSf) * ln_w[tt] + ln_b[tt];
        lns[grp][tt + 1] = ln;
        __syncthreads();
        float l0 = lns[grp][tt], l1 = lns[grp][tt + 1], l2 = lns[grp][tt + 2];
        g_u[node * IND + tt] = conv_w[0] * l0 + conv_w[1] * l1 + conv_w[2] * l2;
        g_v[node * IND + tt] = conv_w[3] * l0 + conv_w[4] * l1 + conv_w[5] * l2;
    } else {
        // ---- bucket: hist + scan + scatter (one block, 512 threads) ----
        int* cnt = (int*)smraw;                 // [2048]
        int* warpsum = cnt + 2048;              // [16]
        cnt[t] = 0; cnt[t + 512] = 0; cnt[t + 1024] = 0; cnt[t + 1536] = 0;
        __syncthreads();
        for (int e = t; e < Ee; e += 512) atomicAdd(&cnt[src[e]], 1);
        __syncthreads();

        int base = t * 4;
        int loc[4];
        int s = 0;
#pragma unroll
        for (int i = 0; i < 4; i++) { loc[i] = cnt[base + i]; s += loc[i]; }
        int lane = t & 31, warp = t >> 5;       // 16 warps
        int v = s;
#pragma unroll
        for (int o = 1; o < 32; o <<= 1) {
            int u = __shfl_up_sync(0xffffffffu, v, o);
            if (lane >= o) v += u;
        }
        if (lane == 31) warpsum[warp] = v;
        __syncthreads();
        if (t == 0) {
            int run = 0;
            for (int i = 0; i < 16; i++) { int x = warpsum[i]; warpsum[i] = run; run += x; }
        }
        __syncthreads();
        int run = v - s + warpsum[warp];
#pragma unroll
        for (int i = 0; i < 4; i++) {
            g_off[base + i] = run;
            cnt[base + i] = run;
            run += loc[i];
        }
        if (t == 511) g_off[Nn] = run;
        __syncthreads();
        for (int e = t; e < Ee; e += 512) {
            int p = atomicAdd(&cnt[src[e]], 1);
            g_eidx[p] = e;
        }
    }
}

// ================= p1 GEMM: frag-packed tf32, LDS.128 mainloop, cp.async 2-stage =================
#define BST 12
#define STG_U4 (2 * 128 * BST)
#define P1M_SMEM (2 * STG_U4 * 16)     /* 98304 */
#define NCHUNK 8

__global__ __launch_bounds__(256) void k_p1mm(const float* __restrict__ b1,
                                              const float* __restrict__ bp2) {
    extern __shared__ uint4 smq[];
    int tid = threadIdx.x;
    int wid = tid >> 5, lane = tid & 31;
    int g = lane >> 2, t = lane & 3;
    int warp_m = (wid >> 2) * 64;
    int warp_n = (wid & 3) * 32;
    int bx = blockIdx.x;
    int row0 = blockIdx.y * 128;
    int col0 = bx * 128;
    bool p2tile = (bx == 32);

    uint32_t sb = smem_u32(smq);

    int lm[4], lq[4];
#pragma unroll
    for (int it = 0; it < 4; it++) {
        int idx = tid + it * 256;
        lm[it] = idx >> 3;
        lq[it] = idx & 7;
    }

    float acc[4][4][4];
#pragma unroll
    for (int mi = 0; mi < 4; mi++)
#pragma unroll
        for (int ni = 0; ni < 4; ni++)
#pragma unroll
            for (int r = 0; r < 4; r++) acc[mi][ni][r] = 0.f;

#pragma unroll
    for (int it = 0; it < 4; it++)
        cp_async16(sb + (lm[it] * BST + lq[it]) * 16, &g_A2p[(row0 + lm[it]) * 64 + lq[it]]);
#pragma unroll
    for (int it = 0; it < 4; it++)
        cp_async16(sb + (128 * BST + lm[it] * BST + lq[it]) * 16,
                   &g_B2p[(size_t)(col0 + lm[it]) * 64 + lq[it]]);
    CP_COMMIT();

    for (int c = 0; c < NCHUNK; c++) {
        if (c + 1 < NCHUNK) {
            int q0 = (c + 1) * 8;
            uint32_t s1 = sb + ((c + 1) & 1) * STG_U4 * 16;
#pragma unroll
            for (int it = 0; it < 4; it++)
                cp_async16(s1 + (lm[it] * BST + lq[it]) * 16,
                           &g_A2p[(row0 + lm[it]) * 64 + q0 + lq[it]]);
#pragma unroll
            for (int it = 0; it < 4; it++)
                cp_async16(s1 + (128 * BST + lm[it] * BST + lq[it]) * 16,
                           &g_B2p[(size_t)(col0 + lm[it]) * 64 + q0 + lq[it]]);
            CP_COMMIT();
            CP_WAIT(1);
        } else {
            CP_WAIT(0);
        }
        __syncthreads();

        uint4* Ap = smq + (c & 1) * STG_U4;
        uint4* Bp = Ap + 128 * BST;
#pragma unroll
        for (int kb2 = 0; kb2 < 2; kb2++) {
            uint4 afr[4][2], bfr[4];
#pragma unroll
            for (int mi = 0; mi < 4; mi++) {
                int r = warp_m + mi * 16 + g;
                afr[mi][0] = Ap[r * BST + kb2 * 4 + t];
                afr[mi][1] = Ap[(r + 8) * BST + kb2 * 4 + t];
            }
#pragma unroll
            for (int ni = 0; ni < 4; ni++)
                bfr[ni] = Bp[(warp_n + ni * 8 + g) * BST + kb2 * 4 + t];
#pragma unroll
            for (int mi = 0; mi < 4; mi++) {
                uint32_t ah[4] = {afr[mi][0].x, afr[mi][1].x, afr[mi][0].y, afr[mi][1].y};
                uint32_t al[4] = {afr[mi][0].z, afr[mi][1].z, afr[mi][0].w, afr[mi][1].w};
#pragma unroll
                for (int ni = 0; ni < 4; ni++) {
                    uint32_t bh2[2] = {bfr[ni].x, bfr[ni].y};
                    uint32_t bl2[2] = {bfr[ni].z, bfr[ni].w};
                    mma_tf32(acc[mi][ni], ah, bh2);
                    mma_tf32(acc[mi][ni], ah, bl2);
                    mma_tf32(acc[mi][ni], al, bh2);
                }
            }
        }
        __syncthreads();
    }

    if (!p2tile) {
#pragma unroll
        for (int mi = 0; mi < 4; mi++) {
            int r = row0 + warp_m + mi * 16 + g;
#pragma unroll
            for (int ni = 0; ni < 4; ni++) {
                int c = col0 + warp_n + ni * 8 + t * 2;
                float2 bb = *(const float2*)&b1[c];
                float2 o0, o1;
                o0.x = fmaxf(acc[mi][ni][0] + bb.x, 0.f);
                o0.y = fmaxf(acc[mi][ni][1] + bb.y, 0.f);
                o1.x = fmaxf(acc[mi][ni][2] + bb.x, 0.f);
                o1.y = fmaxf(acc[mi][ni][3] + bb.y, 0.f);
                *(float2*)&g_p1[(size_t)r * NOUT + c] = o0;
                *(float2*)&g_p1[(size_t)(r + 8) * NOUT + c] = o1;
            }
        }
    } else {
#pragma unroll
        for (int mi = 0; mi < 4; mi++) {
            int r = row0 + warp_m + mi * 16 + g;
#pragma unroll
            for (int ni = 0; ni < 4; ni++) {
                int c = warp_n + ni * 8 + t * 2;
                if (c < HIDD) {
                    float2 bb = *(const float2*)&bp2[c];
                    float2 o0, o1;
                    o0.x = fmaxf(acc[mi][ni][0] + bb.x, 0.f);
                    o0.y = fmaxf(acc[mi][ni][1] + bb.y, 0.f);
                    o1.x = fmaxf(acc[mi][ni][2] + bb.x, 0.f);
                    o1.y = fmaxf(acc[mi][ni][3] + bb.y, 0.f);
                    *(float2*)&g_p2[r * HIDD + c] = o0;
                    *(float2*)&g_p2[(r + 8) * HIDD + c] = o1;
                }
            }
        }
    }
}

// ================= local branch v3: fully packed, zero cvt in mainloop =================
#define TPK_STR 68
#define L3_SMEM ((32 * TPK_STR + 64 * TPK_STR) * 16)

__global__ __launch_bounds__(256) void k_local3(const int* __restrict__ src,
                                                const int* __restrict__ dst,
                                                const float* __restrict__ conv_b,
                                                const float* __restrict__ b2,
                                                const float* __restrict__ bnL_g,
                                                const float* __restrict__ bnL_b,
                                                const float* __restrict__ ein,
                                                float* __restrict__ out) {
    extern __shared__ char smraw[];
    uint4* Tpk = (uint4*)smraw;
    uint4* W2p = (uint4*)(smraw + 32 * TPK_STR * 16);

    int tid = threadIdx.x;
    int e0 = blockIdx.x * 32;
    float cb = conv_b[0];

#pragma unroll
    for (int it = 0; it < 2; it++) {
        int idx = tid + it * 256;
        int e = idx >> 4, kb = idx & 15;
        int se = src[e0 + e], de = dst[e0 + e];
        const float4* pu = (const float4*)&g_u[se * IND + kb * 8];
        const float4* pv = (const float4*)&g_v[de * IND + kb * 8];
        float4 u0 = pu[0], u1 = pu[1], v0 = pv[0], v1 = pv[1];
        float xv[8] = {u0.x + v0.x + cb, u0.y + v0.y + cb, u0.z + v0.z + cb, u0.w + v0.w + cb,
                       u1.x + v1.x + cb, u1.y + v1.y + cb, u1.z + v1.z + cb, u1.w + v1.w + cb};
        uint32_t hi[8], lo[8];
#pragma unroll
        for (int j = 0; j < 8; j++) {
            float x = fmaxf(xv[j], 0.f);
            hi[j] = f2tf(x);
            lo[j] = f2tf(x - __uint_as_float(hi[j]));
        }
#pragma unroll
        for (int tq = 0; tq < 4; tq++)
            Tpk[e * TPK_STR + kb * 4 + tq] = make_uint4(hi[tq], hi[tq + 4], lo[tq], lo[tq + 4]);
    }
#pragma unroll
    for (int it = 0; it < 16; it++) {
        int idx = tid + it * 256;
        int n = idx >> 6, c = idx & 63;
        W2p[n * TPK_STR + c] = g_w2pk[n * 64 + c];
    }
    __syncthreads();

    int wid = tid >> 5, lane = tid & 31;
    int g = lane >> 2, t = lane & 3;
    int m0 = (wid & 1) * 16;
    int n0 = (wid >> 1) * 16;
    int r = m0 + g;

    float acc[2][4];
#pragma unroll
    for (int ni = 0; ni < 2; ni++)
#pragma unroll
        for (int q = 0; q < 4; q++) acc[ni][q] = 0.f;

#pragma unroll 4
    for (int kb = 0; kb < 16; kb++) {
        uint4 a0 = Tpk[r * TPK_STR + kb * 4 + t];
        uint4 a1 = Tpk[(r + 8) * TPK_STR + kb * 4 + t];
        uint32_t ah[4] = {a0.x, a1.x, a0.y, a1.y};
        uint32_t al[4] = {a0.z, a1.z, a0.w, a1.w};
#pragma unroll
        for (int ni = 0; ni < 2; ni++) {
            uint4 bfr = W2p[(n0 + ni * 8 + g) * TPK_STR + kb * 4 + t];
            uint32_t bh2[2] = {bfr.x, bfr.y};
            uint32_t bl2[2] = {bfr.z, bfr.w};
            mma_tf32(acc[ni], ah, bh2);
            mma_tf32(acc[ni], ah, bl2);
            mma_tf32(acc[ni], al, bh2);
        }
    }

    float rs = rsqrtf(1.f + EPSf);
    int ea = e0 + m0 + g, eb = ea + 8;
#pragma unroll
    for (int ni = 0; ni < 2; ni++) {
        int c = n0 + ni * 8 + t * 2;
        float2 bb = *(const float2*)&b2[c];
        float2 gg = *(const float2*)&bnL_g[c];
        float2 bL = *(const float2*)&bnL_b[c];
        float2 ia = *(const float2*)&ein[ea * HIDD + c];
        float2 ib = *(const float2*)&ein[eb * HIDD + c];
        float2 oa, ob;
        oa.x = fmaxf((acc[ni][0] + bb.x) * (gg.x * rs) + bL.x, 0.f) + ia.x;
        oa.y = fmaxf((acc[ni][1] + bb.y) * (gg.y * rs) + bL.y, 0.f) + ia.y;
        ob.x = fmaxf((acc[ni][2] + bb.x) * (gg.x * rs) + bL.x, 0.f) + ib.x;
        ob.y = fmaxf((acc[ni][3] + bb.y) * (gg.y * rs) + bL.y, 0.f) + ib.y;
        *(float2*)&out[ea * HIDD + c] = oa;
        *(float2*)&out[eb * HIDD + c] = ob;
    }
}

// ================= global branch fused =================
#define GA_STR 68
#define ECAP 64
#define GO_AS  0
#define GO_BHI (64 * GA_STR * 4)
#define GO_BLO (GO_BHI + 64 * 72 * 4)
#define GO_P2  (GO_BLO + 64 * 72 * 4)
#define GO_EIX (GO_P2 + ECAP * 64 * 4)
#define G2_SMEM (GO_EIX + ECAP * 4)

__global__ __launch_bounds__(256) void k_global2(const int* __restrict__ dst,
                                                 float* __restrict__ out) {
    extern __shared__ char smraw[];
    float* As = (float*)(smraw + GO_AS);
    float* Gs = As;
    uint32_t* Bhi = (uint32_t*)(smraw + GO_BHI);
    uint32_t* Blo = (uint32_t*)(smraw + GO_BLO);
    float* p2buf = (float*)(smraw + GO_P2);
    int* eixs = (int*)(smraw + GO_EIX);

    int node = blockIdx.x;
    int tid = threadIdx.x;
    int beg = g_off[node], end = g_off[node + 1];
    if (beg == end) return;

    int ec = min(end - beg, ECAP);
    for (int idx = tid; idx < ec * 64; idx += 256) {
        int ei = idx >> 6, d2 = idx & 63;
        int e = g_eidx[beg + ei];
        if (d2 == 0) eixs[ei] = e;
        p2buf[idx] = g_p2[dst[e] * HIDD + d2];
    }

    const float* p1row = &g_p1[(size_t)node * NOUT];
#pragma unroll
    for (int it = 0; it < 16; it++) {
        int idx = tid + it * 256;
        int d = idx >> 6, k = idx & 63;
        As[k * GA_STR + d] = p1row[idx];
    }
#pragma unroll
    for (int it = 0; it < 16; it++) {
        int idx = tid + it * 256;
        int d = idx >> 6, dp = idx & 63;
        Bhi[d * 72 + dp] = g_wghi[idx];
        Blo[d * 72 + dp] = g_wglo[idx];
    }
    __syncthreads();

    int wid = tid >> 5, lane = tid & 31;
    int g = lane >> 2, t = lane & 3;
    int m0 = (wid & 3) * 16;
    int n0 = (wid >> 2) * 32;

    float acc[4][4];
#pragma unroll
    for (int ni = 0; ni < 4; ni++)
#pragma unroll
        for (int r = 0; r < 4; r++) acc[ni][r] = 0.f;

#pragma unroll
    for (int ks = 0; ks < 64; ks += 8) {
        uint32_t ahi[4], alo[4], bh[4][2], bl[4][2];
        int r = m0 + g;
        float a0 = As[r * GA_STR + ks + t];
        float a1 = As[(r + 8) * GA_STR + ks + t];
        float a2 = As[r * GA_STR + ks + t + 4];
        float a3 = As[(r + 8) * GA_STR + ks + t + 4];
        ahi[0] = f2tf(a0); alo[0] = f2tf(a0 - __uint_as_float(ahi[0]));
        ahi[1] = f2tf(a1); alo[1] = f2tf(a1 - __uint_as_float(ahi[1]));
        ahi[2] = f2tf(a2); alo[2] = f2tf(a2 - __uint_as_float(ahi[2]));
        ahi[3] = f2tf(a3); alo[3] = f2tf(a3 - __uint_as_float(ahi[3]));
#pragma unroll
        for (int ni = 0; ni < 4; ni++) {
            int n = n0 + ni * 8 + g;
            bh[ni][0] = Bhi[(ks + t) * 72 + n];
            bh[ni][1] = Bhi[(ks + t + 4) * 72 + n];
            bl[ni][0] = Blo[(ks + t) * 72 + n];
            bl[ni][1] = Blo[(ks + t + 4) * 72 + n];
        }
#pragma unroll
        for (int ni = 0; ni < 4; ni++) {
            mma_tf32(acc[ni], ahi, bh[ni]);
            mma_tf32(acc[ni], ahi, bl[ni]);
            mma_tf32(acc[ni], alo, bh[ni]);
        }
    }
    __syncthreads();

    int m = m0 + g;
#pragma unroll
    for (int ni = 0; ni < 4; ni++) {
        int n = n0 + ni * 8 + t * 2;
        Gs[m * 65 + n] = acc[ni][0];
        Gs[m * 65 + n + 1] = acc[ni][1];
        Gs[(m + 8) * 65 + n] = acc[ni][2];
        Gs[(m + 8) * 65 + n + 1] = acc[ni][3];
    }
    __syncthreads();

    int d = tid & 63, grp = tid >> 6;
    float Gr[64];
#pragma unroll
    for (int k = 0; k < 64; k++) Gr[k] = Gs[k * 65 + d];
    float Cd = g_C[d];

    int base = beg;
    while (true) {
        for (int e = grp; e < ec; e += 4) {
            const float4* p = (const float4*)&p2buf[e * 64];
            float a2 = 0.f;
#pragma unroll
            for (int k4 = 0; k4 < 16; k4++) {
                float4 v = p[k4];
                a2 += Gr[k4 * 4 + 0] * v.x + Gr[k4 * 4 + 1] * v.y
                    + Gr[k4 * 4 + 2] * v.z + Gr[k4 * 4 + 3] * v.w;
            }
            int eg = eixs[e];
            out[eg * HIDD + d] += fmaxf(a2 + Cd, 0.f);
        }
        base += ec;
        if (base >= end) break;
        __syncthreads();
        ec = min(end - base, ECAP);
        for (int idx = tid; idx < ec * 64; idx += 256) {
            int ei = idx >> 6, d2 = idx & 63;
            int e = g_eidx[base + ei];
            if (d2 == 0) eixs[ei] = e;
            p2buf[idx] = g_p2[dst[e] * HIDD + d2];
        }
        __syncthreads();
    }
}

// ================= launch =================
extern "C" void kernel_launch(void* const* d_in, const int* in_sizes, int n_in,
                              void* d_out, int out_size) {
    const float* h      = (const float*)d_in[0];
    const float* local_ = (const float*)d_in[1];
    const float* ein    = (const float*)d_in[2];
    const int*   src    = (const int*)d_in[3];
    const int*   dst    = (const int*)d_in[4];
    const float* ln_w   = (const float*)d_in[5];
    const float* ln_b   = (const float*)d_in[6];
    const float* conv_w = (const float*)d_in[7];
    const float* conv_b = (const float*)d_in[8];
    const float* W1     = (const float*)d_in[9];
    const float* b1     = (const float*)d_in[10];
    const float* Wp2    = (const float*)d_in[11];
    const float* bp2    = (const float*)d_in[12];
    const float* W2     = (const float*)d_in[13];
    const float* b2     = (const float*)d_in[14];
    const float* W3     = (const float*)d_in[15];
    const float* b3     = (const float*)d_in[16];
    const float* bng_g  = (const float*)d_in[17];
    const float* bng_b  = (const float*)d_in[18];
    const float* bnG_g  = (const float*)d_in[19];
    const float* bnG_b  = (const float*)d_in[20];
    const float* bnL_g  = (const float*)d_in[21];
    const float* bnL_b  = (const float*)d_in[22];
    float* out = (float*)d_out;

    static int smem_set = 0;
    if (!smem_set) {
        cudaFuncSetAttribute(k_p1mm, cudaFuncAttributeMaxDynamicSharedMemorySize, P1M_SMEM);
        cudaFuncSetAttribute(k_local3, cudaFuncAttributeMaxDynamicSharedMemorySize, L3_SMEM);
        cudaFuncSetAttribute(k_global2, cudaFuncAttributeMaxDynamicSharedMemorySize, G2_SMEM);
        smem_set = 1;
    }

    k_setup<<<654, 512>>>(h, W1, Wp2, W3, b3, bng_g, bng_b, bnG_g, bnG_b, W2,
                          local_, ln_w, ln_b, conv_w, src);
    k_p1mm<<<dim3(33, Nn / 128), 256, P1M_SMEM>>>(b1, bp2);
    k_local3<<<Ee / 32, 256, L3_SMEM>>>(src, dst, conv_b, b2, bnL_g, bnL_b, ein, out);
    k_global2<<<Nn, 256, G2_SMEM>>>(dst, out);   // 4th -> profiled
}